// round 1
// baseline (speedup 1.0000x reference)
#include <cuda_runtime.h>
#include <cstddef>

// Problem constants
#define Bc 8
#define Tc 2048
#define Dc 256
#define Hc 4
#define HDc 64
#define FFNc 1024
#define QT 32
#define KT 64

// -------- scratch (static device arrays: allocation-free) --------
__device__ float g_qkv[(size_t)Bc * Tc * 3 * Dc];        // 50 MB
__device__ float g_E[(size_t)Bc * Hc * Tc * Tc];         // 512 MB unnormalized exp(scores)
__device__ float g_Dinv[Bc * Hc * Tc];                   // per-row 1/denominator
__device__ float g_attn[(size_t)Bc * Tc * Dc];           // attention output (B,T,D)
__device__ float g_proj[(size_t)Bc * Tc * Dc];
__device__ float g_h[(size_t)Bc * Tc * Dc];
__device__ float g_f[(size_t)Bc * Tc * FFNc];            // 64 MB FFN hidden
__device__ float g_ffn[(size_t)Bc * Tc * Dc];
__device__ float g_hraw[Bc * Tc];                        // halting accumulator

// =====================================================================
// Tiled fp32 GEMM:  C[M,N] = A[M,K] * W[N,K]^T + bias[N]   (optional ReLU)
// BM=BN=64, BK=16, 256 threads, 4x4 register tile per thread.
// =====================================================================
template <bool RELU>
__global__ __launch_bounds__(256) void gemm_tn(const float* __restrict__ A,
                                               const float* __restrict__ W,
                                               const float* __restrict__ bias,
                                               float* __restrict__ C,
                                               int M, int N, int K) {
    constexpr int BM = 64, BN = 64, BK = 16;
    __shared__ float As[BK][BM + 4];
    __shared__ float Bs[BK][BN + 4];
    const int t = threadIdx.x;
    const int row0 = blockIdx.y * BM, col0 = blockIdx.x * BN;
    const int tr = t >> 4, tc = t & 15;          // 16x16 compute layout
    const int lr = t >> 2, lc = (t & 3) << 2;    // load layout: 64 rows x 4 float4

    float acc[4][4] = {};
    for (int k0 = 0; k0 < K; k0 += BK) {
        float4 a4 = *(const float4*)(A + (size_t)(row0 + lr) * K + k0 + lc);
        float4 b4 = *(const float4*)(W + (size_t)(col0 + lr) * K + k0 + lc);
        __syncthreads();
        As[lc + 0][lr] = a4.x; As[lc + 1][lr] = a4.y; As[lc + 2][lr] = a4.z; As[lc + 3][lr] = a4.w;
        Bs[lc + 0][lr] = b4.x; Bs[lc + 1][lr] = b4.y; Bs[lc + 2][lr] = b4.z; Bs[lc + 3][lr] = b4.w;
        __syncthreads();
#pragma unroll
        for (int kk = 0; kk < BK; ++kk) {
            const float4 av = *(const float4*)&As[kk][tr << 2];
            const float4 bv = *(const float4*)&Bs[kk][tc << 2];
            acc[0][0] += av.x * bv.x; acc[0][1] += av.x * bv.y; acc[0][2] += av.x * bv.z; acc[0][3] += av.x * bv.w;
            acc[1][0] += av.y * bv.x; acc[1][1] += av.y * bv.y; acc[1][2] += av.y * bv.z; acc[1][3] += av.y * bv.w;
            acc[2][0] += av.z * bv.x; acc[2][1] += av.z * bv.y; acc[2][2] += av.z * bv.z; acc[2][3] += av.z * bv.w;
            acc[3][0] += av.w * bv.x; acc[3][1] += av.w * bv.y; acc[3][2] += av.w * bv.z; acc[3][3] += av.w * bv.w;
        }
    }
    const float4 bias4 = *(const float4*)(bias + col0 + (tc << 2));
#pragma unroll
    for (int i = 0; i < 4; ++i) {
        float4 o;
        o.x = acc[i][0] + bias4.x; o.y = acc[i][1] + bias4.y;
        o.z = acc[i][2] + bias4.z; o.w = acc[i][3] + bias4.w;
        if (RELU) {
            o.x = fmaxf(o.x, 0.f); o.y = fmaxf(o.y, 0.f);
            o.z = fmaxf(o.z, 0.f); o.w = fmaxf(o.w, 0.f);
        }
        *(float4*)(C + (size_t)(row0 + (tr << 2) + i) * N + col0 + (tc << 2)) = o;
    }
}

// =====================================================================
// Attention: one pass, no max-subtraction (scores bounded ~|2|).
// Block = (q-tile of 32, one (b,h)). Computes e=exp(s/8) (0 if masked),
// accumulates denominator d and unnormalized PV; spills e to g_E for the
// halting column-sum kernel. Writes normalized attn to g_attn [B,T,D].
// =====================================================================
__global__ __launch_bounds__(256) void attn_kernel(const float* __restrict__ qkv,
                                                   const float* __restrict__ mask) {
    const int qtile = blockIdx.x, bh = blockIdx.y;
    const int b = bh >> 2, h = bh & 3;
    const int t = threadIdx.x;
    const int qi = t & 31, grp = t >> 5;
    const int qrow = qtile * QT + qi;

    __shared__ float Ks[KT * HDc];          // 16 KB
    __shared__ float Vs[KT * HDc];          // 16 KB
    __shared__ float esh[QT][KT + 1];       // 8.3 KB (padded, conflict-free)
    __shared__ float maskS[KT];
    __shared__ float red[QT * 8];
    __shared__ float invd_sh[QT];

    // Q row in registers (64 floats)
    float4 qv[16];
    const float* qptr = qkv + ((size_t)(b * Tc + qrow)) * (3 * Dc) + h * HDc;
#pragma unroll
    for (int i = 0; i < 16; ++i) qv[i] = *(const float4*)(qptr + 4 * i);

    float dacc = 0.f;
    float acc[8] = {0.f, 0.f, 0.f, 0.f, 0.f, 0.f, 0.f, 0.f};

    for (int kb = 0; kb < Tc; kb += KT) {
        __syncthreads();   // previous PV done before overwriting tiles
#pragma unroll
        for (int it = 0; it < 4; ++it) {
            int i = t + it * 256;                   // float4 index 0..1023
            int row = i >> 4, c = (i & 15) << 2;    // row 0..63, c float offset
            const float* base = qkv + ((size_t)(b * Tc + kb + row)) * (3 * Dc) + h * HDc + c;
            *(float4*)(Ks + (i << 2)) = *(const float4*)(base + Dc);
            *(float4*)(Vs + (i << 2)) = *(const float4*)(base + 2 * Dc);
        }
        if (t < KT) maskS[t] = mask[b * Tc + kb + t];
        __syncthreads();

        // scores + exp for this thread's 8 keys
        float e8[8];
#pragma unroll
        for (int j = 0; j < 8; ++j) {
            int kj = (grp << 3) + j;
            const float4* kr = (const float4*)(Ks + kj * HDc);
            float s = 0.f;
#pragma unroll
            for (int c = 0; c < 16; ++c) {
                float4 k4 = kr[c];
                s += qv[c].x * k4.x + qv[c].y * k4.y + qv[c].z * k4.z + qv[c].w * k4.w;
            }
            float e = (maskS[kj] > 0.5f) ? 0.f : __expf(s * 0.125f);
            e8[j] = e;
            dacc += e;
            esh[qi][kj] = e;
        }
        // spill e tile to HBM (for halting column sums)
        {
            float* ep = g_E + ((size_t)(bh * Tc + qrow)) * Tc + kb + (grp << 3);
            *(float4*)ep = make_float4(e8[0], e8[1], e8[2], e8[3]);
            *(float4*)(ep + 4) = make_float4(e8[4], e8[5], e8[6], e8[7]);
        }
        __syncthreads();

        // PV: thread owns (qi, d = grp*8 .. +7); Vs reads broadcast within warp
#pragma unroll 8
        for (int kj = 0; kj < KT; ++kj) {
            float w = esh[qi][kj];
            const float4* vr = (const float4*)(Vs + kj * HDc + (grp << 3));
            float4 v0 = vr[0], v1 = vr[1];
            acc[0] += w * v0.x; acc[1] += w * v0.y; acc[2] += w * v0.z; acc[3] += w * v0.w;
            acc[4] += w * v1.x; acc[5] += w * v1.y; acc[6] += w * v1.z; acc[7] += w * v1.w;
        }
    }

    // reduce denominator across the 8 key-groups per query
    red[(qi << 3) + grp] = dacc;
    __syncthreads();
    if (t < QT) {
        float s = 0.f;
#pragma unroll
        for (int j = 0; j < 8; ++j) s += red[(t << 3) + j];
        float inv = 1.f / s;
        invd_sh[t] = inv;
        g_Dinv[bh * Tc + qtile * QT + t] = inv;
    }
    __syncthreads();
    const float inv = invd_sh[qi];
    float* op = g_attn + ((size_t)(b * Tc + qrow)) * Dc + h * HDc + (grp << 3);
    *(float4*)op = make_float4(acc[0] * inv, acc[1] * inv, acc[2] * inv, acc[3] * inv);
    *(float4*)(op + 4) = make_float4(acc[4] * inv, acc[5] * inv, acc[6] * inv, acc[7] * inv);
}

// halting_raw[b,k] = 0.25 * sum_{h,q} e[b,h,q,k] * Dinv[b,h,q]
__global__ __launch_bounds__(256) void colsum_kernel() {
    const int k = blockIdx.x * 256 + threadIdx.x;
    const int b = blockIdx.y, h = blockIdx.z;
    const int bh = b * Hc + h;
    const float* Ep = g_E + (size_t)bh * Tc * Tc + k;
    const float* dp = g_Dinv + bh * Tc;
    float acc = 0.f;
#pragma unroll 8
    for (int q = 0; q < Tc; ++q) acc += Ep[(size_t)q * Tc] * dp[q];
    atomicAdd(&g_hraw[b * Tc + k], 0.25f * acc);
}

// halting = softmax(halting_raw + mask * -1e10) per batch row
__global__ __launch_bounds__(256) void halting_kernel(const float* __restrict__ mask,
                                                      float* __restrict__ out) {
    const int b = blockIdx.x;
    const int t = threadIdx.x;
    __shared__ float es[Tc];
    __shared__ float redm[8], reds[8];
    float lmax = -3.4e38f;
    for (int k = t; k < Tc; k += 256) {
        float v = g_hraw[b * Tc + k] + mask[b * Tc + k] * (-1e10f);
        es[k] = v;
        lmax = fmaxf(lmax, v);
    }
#pragma unroll
    for (int o = 16; o; o >>= 1) lmax = fmaxf(lmax, __shfl_xor_sync(~0u, lmax, o));
    if ((t & 31) == 0) redm[t >> 5] = lmax;
    __syncthreads();
    float bmax = redm[0];
#pragma unroll
    for (int j = 1; j < 8; ++j) bmax = fmaxf(bmax, redm[j]);
    float lsum = 0.f;
    for (int k = t; k < Tc; k += 256) {
        float e = __expf(es[k] - bmax);
        es[k] = e;
        lsum += e;
    }
#pragma unroll
    for (int o = 16; o; o >>= 1) lsum += __shfl_xor_sync(~0u, lsum, o);
    if ((t & 31) == 0) reds[t >> 5] = lsum;
    __syncthreads();
    float bsum = 0.f;
#pragma unroll
    for (int j = 0; j < 8; ++j) bsum += reds[j];
    const float inv = 1.f / bsum;
    for (int k = t; k < Tc; k += 256) out[b * Tc + k] = es[k] * inv;
}

// out = LayerNorm(x + y) * g + be ; one warp per 256-wide row
__global__ __launch_bounds__(256) void addln_kernel(const float* __restrict__ x,
                                                    const float* __restrict__ y,
                                                    const float* __restrict__ g,
                                                    const float* __restrict__ be,
                                                    float* __restrict__ out) {
    const int warp = threadIdx.x >> 5, lane = threadIdx.x & 31;
    const size_t row = (size_t)blockIdx.x * 8 + warp;
    const float* xr = x + row * Dc;
    const float* yr = y + row * Dc;
    float v[8];
    float s = 0.f, sq = 0.f;
#pragma unroll
    for (int i = 0; i < 8; ++i) {
        float z = xr[lane + 32 * i] + yr[lane + 32 * i];
        v[i] = z; s += z; sq += z * z;
    }
#pragma unroll
    for (int o = 16; o; o >>= 1) {
        s += __shfl_xor_sync(~0u, s, o);
        sq += __shfl_xor_sync(~0u, sq, o);
    }
    const float mean = s * (1.f / Dc);
    const float var = sq * (1.f / Dc) - mean * mean;
    const float rstd = rsqrtf(var + 1e-5f);
    float* orow = out + row * Dc;
#pragma unroll
    for (int i = 0; i < 8; ++i) {
        int c = lane + 32 * i;
        orow[c] = (v[i] - mean) * rstd * g[c] + be[c];
    }
}

__global__ void zero_hraw() {
    int i = blockIdx.x * 256 + threadIdx.x;
    if (i < Bc * Tc) g_hraw[i] = 0.f;
}

// =====================================================================
extern "C" void kernel_launch(void* const* d_in, const int* in_sizes, int n_in,
                              void* d_out, int out_size) {
    (void)in_sizes; (void)n_in; (void)out_size;
    const float* x    = (const float*)d_in[0];
    const float* mask = (const float*)d_in[1];
    const float* Wqkv = (const float*)d_in[2];
    const float* bqkv = (const float*)d_in[3];
    const float* Wo   = (const float*)d_in[4];
    const float* bo   = (const float*)d_in[5];
    const float* W1   = (const float*)d_in[6];
    const float* b1   = (const float*)d_in[7];
    const float* W2   = (const float*)d_in[8];
    const float* b2   = (const float*)d_in[9];
    const float* g1   = (const float*)d_in[10];
    const float* be1  = (const float*)d_in[11];
    const float* g2   = (const float*)d_in[12];
    const float* be2  = (const float*)d_in[13];
    float* out  = (float*)d_out;
    float* halt = out + (size_t)Bc * Tc * Dc;

    float *p_qkv, *p_attn, *p_proj, *p_h, *p_f, *p_ffn;
    cudaGetSymbolAddress((void**)&p_qkv,  g_qkv);
    cudaGetSymbolAddress((void**)&p_attn, g_attn);
    cudaGetSymbolAddress((void**)&p_proj, g_proj);
    cudaGetSymbolAddress((void**)&p_h,    g_h);
    cudaGetSymbolAddress((void**)&p_f,    g_f);
    cudaGetSymbolAddress((void**)&p_ffn,  g_ffn);

    const int MR = Bc * Tc;  // 16384 rows

    zero_hraw<<<64, 256>>>();
    // QKV projection: [16384,256] x [768,256]^T
    gemm_tn<false><<<dim3(3 * Dc / 64, MR / 64), 256>>>(x, Wqkv, bqkv, p_qkv, MR, 3 * Dc, Dc);
    // Attention (writes g_E, g_Dinv, g_attn)
    attn_kernel<<<dim3(Tc / QT, Bc * Hc), 256>>>(p_qkv, mask);
    // Halting column sums + softmax
    colsum_kernel<<<dim3(Tc / 256, Bc, Hc), 256>>>();
    halting_kernel<<<Bc, 256>>>(mask, halt);
    // Output projection + residual LN1
    gemm_tn<false><<<dim3(Dc / 64, MR / 64), 256>>>(p_attn, Wo, bo, p_proj, MR, Dc, Dc);
    addln_kernel<<<MR / 8, 256>>>(x, p_proj, g1, be1, p_h);
    // FFN
    gemm_tn<true><<<dim3(FFNc / 64, MR / 64), 256>>>(p_h, W1, b1, p_f, MR, FFNc, Dc);
    gemm_tn<false><<<dim3(Dc / 64, MR / 64), 256>>>(p_f, W2, b2, p_ffn, MR, Dc, FFNc);
    addln_kernel<<<MR / 8, 256>>>(p_h, p_ffn, g2, be2, out);
}

// round 3
// speedup vs baseline: 4.3751x; 4.3751x over previous
#include <cuda_runtime.h>
#include <cuda_fp16.h>
#include <cstdint>
#include <cstddef>

#define Bc 8
#define Tc 2048
#define Dc 256
#define Hc 4
#define FFNc 1024

// ---------------- scratch (static device arrays) ----------------
__device__ __half g_xh[(size_t)Bc * Tc * Dc];
__device__ __half g_qkvh[(size_t)Bc * Tc * 3 * Dc];
__device__ __half g_Eh[(size_t)Bc * Hc * Tc * Tc];      // 268 MB exp(scores) fp16
__device__ __half g_vth[(size_t)Bc * Hc * 64 * Tc];     // V^T fp16 [bh][d][k]
__device__ __half g_attnh[(size_t)Bc * Tc * Dc];
__device__ __half g_hh[(size_t)Bc * Tc * Dc];
__device__ __half g_fh[(size_t)Bc * Tc * FFNc];
__device__ __half g_wqkvh[3 * Dc * Dc];
__device__ __half g_woh[Dc * Dc];
__device__ __half g_w1h[FFNc * Dc];
__device__ __half g_w2h[Dc * FFNc];
__device__ float g_d[Bc * Hc * Tc];
__device__ float g_Dinv[Bc * Hc * Tc];
__device__ float g_proj[(size_t)Bc * Tc * Dc];
__device__ float g_h[(size_t)Bc * Tc * Dc];
__device__ float g_ffn[(size_t)Bc * Tc * Dc];
__device__ float g_hraw[Bc * Tc];

// ---------------- helpers ----------------
__device__ __forceinline__ uint32_t s2u(const void* p) {
    uint32_t a;
    asm("{ .reg .u64 t; cvta.to.shared.u64 t, %1; cvt.u32.u64 %0, t; }" : "=r"(a) : "l"(p));
    return a;
}
#define CP_ASYNC16(dst, src) \
    asm volatile("cp.async.cg.shared.global [%0], [%1], 16;" :: "r"(dst), "l"(src))

__device__ __forceinline__ void ldm_x4(uint32_t* r, uint32_t addr) {
    asm volatile("ldmatrix.sync.aligned.m8n8.x4.shared.b16 {%0,%1,%2,%3}, [%4];"
                 : "=r"(r[0]), "=r"(r[1]), "=r"(r[2]), "=r"(r[3]) : "r"(addr));
}
__device__ __forceinline__ void mma16816(float* c, const uint32_t* a, const uint32_t* b) {
    asm volatile("mma.sync.aligned.m16n8k16.row.col.f32.f16.f16.f32 "
                 "{%0,%1,%2,%3}, {%4,%5,%6,%7}, {%8,%9}, {%0,%1,%2,%3};"
                 : "+f"(c[0]), "+f"(c[1]), "+f"(c[2]), "+f"(c[3])
                 : "r"(a[0]), "r"(a[1]), "r"(a[2]), "r"(a[3]), "r"(b[0]), "r"(b[1]));
}

// ---------------- fp16 mma.sync GEMM core ----------------
// C[128 x BN] tile of A[M,K] * B[N,K]^T. BK=64 halves (128B rows, XOR swizzle).
// 256 threads = 8 warps as 2(M) x 4(N); warp tile 64 x (BN/4).
template <int BN>
__device__ __forceinline__ void gemm_core(const __half* __restrict__ Ag, int lda,
                                          const __half* __restrict__ Bg, int ldb,
                                          int K, int m0, int n0,
                                          float (&acc)[4][BN / 32][4]) {
    extern __shared__ char smem_raw[];
    constexpr int NT8 = BN / 32;
    const int tid = threadIdx.x, lane = tid & 31, wid = tid >> 5;
    const int wm = (wid >> 2) * 64;
    const int wn = (wid & 3) * (BN / 4);
    const uint32_t sA = s2u(smem_raw);
    const uint32_t sB = sA + 2 * 128 * 128;
    const int NKT = K >> 6;

#pragma unroll
    for (int mt = 0; mt < 4; ++mt)
#pragma unroll
        for (int nt = 0; nt < NT8; ++nt)
#pragma unroll
            for (int i = 0; i < 4; ++i) acc[mt][nt][i] = 0.f;

    auto loadA = [&](int kt, int buf) {
        const __half* s0 = Ag + (size_t)m0 * lda + kt * 64;
        uint32_t d0 = sA + buf * (128 * 128);
#pragma unroll
        for (int i = 0; i < 4; ++i) {
            int ch = i * 256 + tid;
            int r = ch >> 3, c = ch & 7;
            CP_ASYNC16(d0 + r * 128 + ((c ^ (r & 7)) << 4), s0 + (size_t)r * lda + c * 8);
        }
    };
    auto loadB = [&](int kt, int buf) {
        const __half* s0 = Bg + (size_t)n0 * ldb + kt * 64;
        uint32_t d0 = sB + buf * (BN * 128);
#pragma unroll
        for (int i = 0; i < NT8; ++i) {
            int ch = i * 256 + tid;
            int r = ch >> 3, c = ch & 7;
            CP_ASYNC16(d0 + r * 128 + ((c ^ (r & 7)) << 4), s0 + (size_t)r * ldb + c * 8);
        }
    };

    loadA(0, 0); loadB(0, 0);
    asm volatile("cp.async.commit_group;");

    for (int t = 0; t < NKT; ++t) {
        const int buf = t & 1;
        if (t + 1 < NKT) {
            loadA(t + 1, buf ^ 1); loadB(t + 1, buf ^ 1);
            asm volatile("cp.async.commit_group;");
            asm volatile("cp.async.wait_group 1;");
        } else {
            asm volatile("cp.async.wait_group 0;");
        }
        __syncthreads();
        const uint32_t cA = sA + buf * (128 * 128);
        const uint32_t cB = sB + buf * (BN * 128);
#pragma unroll
        for (int ks = 0; ks < 4; ++ks) {
            uint32_t af[4][4];
#pragma unroll
            for (int mt = 0; mt < 4; ++mt) {
                int m = wm + mt * 16 + (lane & 15);
                int ck = ks * 2 + (lane >> 4);
                ldm_x4(af[mt], cA + m * 128 + ((ck ^ (m & 7)) << 4));
            }
            uint32_t bf[NT8][2];
#pragma unroll
            for (int g = 0; g < NT8 / 2; ++g) {
                uint32_t r4[4];
                int n = wn + g * 16 + (lane & 15);
                int ck = ks * 2 + (lane >> 4);
                ldm_x4(r4, cB + n * 128 + ((ck ^ (n & 7)) << 4));
                bf[2 * g][0] = r4[0]; bf[2 * g][1] = r4[2];
                bf[2 * g + 1][0] = r4[1]; bf[2 * g + 1][1] = r4[3];
            }
#pragma unroll
            for (int mt = 0; mt < 4; ++mt)
#pragma unroll
                for (int nt = 0; nt < NT8; ++nt) mma16816(acc[mt][nt], af[mt], bf[nt]);
        }
        __syncthreads();
    }
}

// ---------------- projection GEMM (+bias, opt ReLU, fp16/fp32 outs) ----------------
__global__ __launch_bounds__(256) void gemm_proj_k(const __half* __restrict__ A,
                                                   const __half* __restrict__ Bw,
                                                   const float* __restrict__ bias,
                                                   __half* __restrict__ Ch, float* __restrict__ Cf,
                                                   int lda, int ldb, int ldc, int K, int relu) {
    float acc[4][4][4];
    const int m0 = blockIdx.y * 128, n0 = blockIdx.x * 128;
    gemm_core<128>(A, lda, Bw, ldb, K, m0, n0, acc);
    const int lane = threadIdx.x & 31, wid = threadIdx.x >> 5;
    const int wm = (wid >> 2) * 64, wn = (wid & 3) * 32;
#pragma unroll
    for (int mt = 0; mt < 4; ++mt) {
        int r = m0 + wm + mt * 16 + (lane >> 2);
#pragma unroll
        for (int nt = 0; nt < 4; ++nt) {
            int col = n0 + wn + nt * 8 + 2 * (lane & 3);
            float bx = __ldg(bias + col), by = __ldg(bias + col + 1);
            float v0 = acc[mt][nt][0] + bx, v1 = acc[mt][nt][1] + by;
            float v2 = acc[mt][nt][2] + bx, v3 = acc[mt][nt][3] + by;
            if (relu) {
                v0 = fmaxf(v0, 0.f); v1 = fmaxf(v1, 0.f);
                v2 = fmaxf(v2, 0.f); v3 = fmaxf(v3, 0.f);
            }
            if (Ch) {
                *(__half2*)(Ch + (size_t)r * ldc + col) = __floats2half2_rn(v0, v1);
                *(__half2*)(Ch + (size_t)(r + 8) * ldc + col) = __floats2half2_rn(v2, v3);
            }
            if (Cf) {
                *(float2*)(Cf + (size_t)r * ldc + col) = make_float2(v0, v1);
                *(float2*)(Cf + (size_t)(r + 8) * ldc + col) = make_float2(v2, v3);
            }
        }
    }
}

// ---------------- scores: E = exp((QK^T)/8) masked -> fp16 + rowsum atomics ----------------
__global__ __launch_bounds__(256) void gemm_score_k(const __half* __restrict__ qkvh,
                                                    const float* __restrict__ mask) {
    float acc[4][4][4];
    const int bh = blockIdx.z, b = bh >> 2, h = bh & 3;
    const int m0 = blockIdx.y * 128, n0 = blockIdx.x * 128;
    const __half* Q = qkvh + (size_t)b * Tc * 768 + h * 64;
    const __half* Kp = Q + 256;
    gemm_core<128>(Q, 768, Kp, 768, 64, m0, n0, acc);
    const int lane = threadIdx.x & 31, wid = threadIdx.x >> 5;
    const int wm = (wid >> 2) * 64, wn = (wid & 3) * 32;
    const float* mp = mask + b * Tc;
    __half* Ebh = g_Eh + (size_t)bh * Tc * Tc;
    float* dbh = g_d + bh * Tc;
#pragma unroll
    for (int mt = 0; mt < 4; ++mt) {
        int r = m0 + wm + mt * 16 + (lane >> 2);
        float rs0 = 0.f, rs1 = 0.f;
#pragma unroll
        for (int nt = 0; nt < 4; ++nt) {
            int col = n0 + wn + nt * 8 + 2 * (lane & 3);
            bool k0m = __ldg(mp + col) > 0.5f, k1m = __ldg(mp + col + 1) > 0.5f;
            float e0 = k0m ? 0.f : __expf(acc[mt][nt][0] * 0.125f);
            float e1 = k1m ? 0.f : __expf(acc[mt][nt][1] * 0.125f);
            float e2 = k0m ? 0.f : __expf(acc[mt][nt][2] * 0.125f);
            float e3 = k1m ? 0.f : __expf(acc[mt][nt][3] * 0.125f);
            rs0 += e0 + e1; rs1 += e2 + e3;
            *(__half2*)(Ebh + (size_t)r * Tc + col) = __floats2half2_rn(e0, e1);
            *(__half2*)(Ebh + (size_t)(r + 8) * Tc + col) = __floats2half2_rn(e2, e3);
        }
        rs0 += __shfl_xor_sync(~0u, rs0, 1); rs0 += __shfl_xor_sync(~0u, rs0, 2);
        rs1 += __shfl_xor_sync(~0u, rs1, 1); rs1 += __shfl_xor_sync(~0u, rs1, 2);
        if ((lane & 3) == 0) { atomicAdd(dbh + r, rs0); atomicAdd(dbh + r + 8, rs1); }
    }
}

// ---------------- PV: attn = (E * V^T^T) / d -> fp16 ----------------
__global__ __launch_bounds__(256) void gemm_pv_k() {
    float acc[4][2][4];
    const int bh = blockIdx.z, b = bh >> 2, h = bh & 3;
    const int m0 = blockIdx.y * 128;
    const __half* Ep = g_Eh + (size_t)bh * Tc * Tc;
    const __half* Vt = g_vth + (size_t)bh * 64 * Tc;
    gemm_core<64>(Ep, Tc, Vt, Tc, Tc, m0, 0, acc);
    const int lane = threadIdx.x & 31, wid = threadIdx.x >> 5;
    const int wm = (wid >> 2) * 64, wn = (wid & 3) * 16;
#pragma unroll
    for (int mt = 0; mt < 4; ++mt) {
        int r = m0 + wm + mt * 16 + (lane >> 2);
        float d0 = g_Dinv[bh * Tc + r], d1 = g_Dinv[bh * Tc + r + 8];
#pragma unroll
        for (int nt = 0; nt < 2; ++nt) {
            int col = wn + nt * 8 + 2 * (lane & 3);
            *(__half2*)(g_attnh + (size_t)(b * Tc + r) * Dc + h * 64 + col) =
                __floats2half2_rn(acc[mt][nt][0] * d0, acc[mt][nt][1] * d0);
            *(__half2*)(g_attnh + (size_t)(b * Tc + r + 8) * Dc + h * 64 + col) =
                __floats2half2_rn(acc[mt][nt][2] * d1, acc[mt][nt][3] * d1);
        }
    }
}

// ---------------- V transpose: qkvh V -> [bh][d][k] fp16 ----------------
__global__ __launch_bounds__(256) void vt_pack(const __half* __restrict__ qkvh) {
    __shared__ __half tile[64][72];
    const int bh = blockIdx.y, b = bh >> 2, h = bh & 3;
    const int k0 = blockIdx.x * 64;
    const int t = threadIdx.x;
#pragma unroll
    for (int i = 0; i < 16; ++i) {
        int idx = t + i * 256, kk = idx >> 6, d = idx & 63;
        tile[kk][d] = qkvh[(size_t)(b * Tc + k0 + kk) * 768 + 512 + h * 64 + d];
    }
    __syncthreads();
#pragma unroll
    for (int i = 0; i < 16; ++i) {
        int idx = t + i * 256, d = idx >> 6, kk = idx & 63;
        g_vth[(size_t)bh * 64 * Tc + (size_t)d * Tc + k0 + kk] = tile[kk][d];
    }
}

// ---------------- small kernels ----------------
__global__ void f2h_k(const float* __restrict__ s, __half* __restrict__ d, int n2) {
    int i = blockIdx.x * 256 + threadIdx.x;
    if (i < n2) {
        float2 v = ((const float2*)s)[i];
        ((__half2*)d)[i] = __floats2half2_rn(v.x, v.y);
    }
}
__global__ void zero_k() {
    int i = blockIdx.x * 256 + threadIdx.x;
    if (i < Bc * Hc * Tc) g_d[i] = 0.f;
    if (i < Bc * Tc) g_hraw[i] = 0.f;
}
__global__ void dinv_k() {
    int i = blockIdx.x * 256 + threadIdx.x;
    if (i < Bc * Hc * Tc) g_Dinv[i] = 1.f / g_d[i];
}

__global__ __launch_bounds__(256) void colsum_h() {
    const int k0 = blockIdx.x * 512 + threadIdx.x * 2;
    const int bh = blockIdx.y, b = bh >> 2;
    const int qs = blockIdx.z * 512;
    const __half2* Ep = (const __half2*)(g_Eh + ((size_t)(bh * Tc + qs)) * Tc + k0);
    const float* dp = g_Dinv + bh * Tc + qs;
    float a0 = 0.f, a1 = 0.f;
#pragma unroll 8
    for (int q = 0; q < 512; ++q) {
        float2 e = __half22float2(Ep[(size_t)q * (Tc / 2)]);
        float dv = dp[q];
        a0 += e.x * dv;
        a1 += e.y * dv;
    }
    atomicAdd(&g_hraw[b * Tc + k0], 0.25f * a0);
    atomicAdd(&g_hraw[b * Tc + k0 + 1], 0.25f * a1);
}

__global__ __launch_bounds__(256) void halting_k(const float* __restrict__ mask, float* __restrict__ out) {
    const int b = blockIdx.x;
    const int t = threadIdx.x;
    __shared__ float es[Tc];
    __shared__ float redm[8], reds[8];
    float lmax = -3.4e38f;
    for (int k = t; k < Tc; k += 256) {
        float v = g_hraw[b * Tc + k] + mask[b * Tc + k] * (-1e10f);
        es[k] = v;
        lmax = fmaxf(lmax, v);
    }
#pragma unroll
    for (int o = 16; o; o >>= 1) lmax = fmaxf(lmax, __shfl_xor_sync(~0u, lmax, o));
    if ((t & 31) == 0) redm[t >> 5] = lmax;
    __syncthreads();
    float bmax = redm[0];
#pragma unroll
    for (int j = 1; j < 8; ++j) bmax = fmaxf(bmax, redm[j]);
    float lsum = 0.f;
    for (int k = t; k < Tc; k += 256) {
        float e = __expf(es[k] - bmax);
        es[k] = e;
        lsum += e;
    }
#pragma unroll
    for (int o = 16; o; o >>= 1) lsum += __shfl_xor_sync(~0u, lsum, o);
    if ((t & 31) == 0) reds[t >> 5] = lsum;
    __syncthreads();
    float bsum = 0.f;
#pragma unroll
    for (int j = 0; j < 8; ++j) bsum += reds[j];
    const float inv = 1.f / bsum;
    for (int k = t; k < Tc; k += 256) out[b * Tc + k] = es[k] * inv;
}

__global__ __launch_bounds__(256) void addln_k(const float* __restrict__ x, const float* __restrict__ y,
                                               const float* __restrict__ g, const float* __restrict__ be,
                                               float* __restrict__ outf, __half* __restrict__ outh) {
    const int warp = threadIdx.x >> 5, lane = threadIdx.x & 31;
    const size_t row = (size_t)blockIdx.x * 8 + warp;
    const float* xr = x + row * Dc;
    const float* yr = y + row * Dc;
    float v[8];
    float s = 0.f, sq = 0.f;
#pragma unroll
    for (int i = 0; i < 8; ++i) {
        float z = xr[lane + 32 * i] + yr[lane + 32 * i];
        v[i] = z; s += z; sq += z * z;
    }
#pragma unroll
    for (int o = 16; o; o >>= 1) { s += __shfl_xor_sync(~0u, s, o); sq += __shfl_xor_sync(~0u, sq, o); }
    const float mean = s * (1.f / Dc);
    const float var = sq * (1.f / Dc) - mean * mean;
    const float rstd = rsqrtf(var + 1e-5f);
#pragma unroll
    for (int i = 0; i < 8; ++i) {
        int c = lane + 32 * i;
        float o = (v[i] - mean) * rstd * g[c] + be[c];
        if (outf) outf[row * Dc + c] = o;
        if (outh) outh[row * Dc + c] = __float2half(o);
    }
}

// =====================================================================
extern "C" void kernel_launch(void* const* d_in, const int* in_sizes, int n_in,
                              void* d_out, int out_size) {
    (void)in_sizes; (void)n_in; (void)out_size;
    const float* x    = (const float*)d_in[0];
    const float* mask = (const float*)d_in[1];
    const float* Wqkv = (const float*)d_in[2];
    const float* bqkv = (const float*)d_in[3];
    const float* Wo   = (const float*)d_in[4];
    const float* bo   = (const float*)d_in[5];
    const float* W1   = (const float*)d_in[6];
    const float* b1   = (const float*)d_in[7];
    const float* W2   = (const float*)d_in[8];
    const float* b2   = (const float*)d_in[9];
    const float* g1   = (const float*)d_in[10];
    const float* be1  = (const float*)d_in[11];
    const float* g2   = (const float*)d_in[12];
    const float* be2  = (const float*)d_in[13];
    float* out  = (float*)d_out;
    float* halt = out + (size_t)Bc * Tc * Dc;

    __half *p_xh, *p_qkvh, *p_attnh, *p_hh, *p_fh, *p_wqkvh, *p_woh, *p_w1h, *p_w2h;
    float *p_proj, *p_h, *p_ffn;
    cudaGetSymbolAddress((void**)&p_xh, g_xh);
    cudaGetSymbolAddress((void**)&p_qkvh, g_qkvh);
    cudaGetSymbolAddress((void**)&p_attnh, g_attnh);
    cudaGetSymbolAddress((void**)&p_hh, g_hh);
    cudaGetSymbolAddress((void**)&p_fh, g_fh);
    cudaGetSymbolAddress((void**)&p_wqkvh, g_wqkvh);
    cudaGetSymbolAddress((void**)&p_woh, g_woh);
    cudaGetSymbolAddress((void**)&p_w1h, g_w1h);
    cudaGetSymbolAddress((void**)&p_w2h, g_w2h);
    cudaGetSymbolAddress((void**)&p_proj, g_proj);
    cudaGetSymbolAddress((void**)&p_h, g_h);
    cudaGetSymbolAddress((void**)&p_ffn, g_ffn);

    const int SMEM_128 = 65536;  // 2 x (128x128B) A + 2 x (128x128B) B
    const int SMEM_64  = 49152;  // 2 x (128x128B) A + 2 x (64x128B) B
    cudaFuncSetAttribute(gemm_proj_k,  cudaFuncAttributeMaxDynamicSharedMemorySize, SMEM_128);
    cudaFuncSetAttribute(gemm_score_k, cudaFuncAttributeMaxDynamicSharedMemorySize, SMEM_128);
    cudaFuncSetAttribute(gemm_pv_k,    cudaFuncAttributeMaxDynamicSharedMemorySize, SMEM_64);

    const int MR = Bc * Tc;  // 16384

    zero_k<<<256, 256>>>();
    // fp32 -> fp16 packing
    f2h_k<<<(MR * Dc / 2 + 255) / 256, 256>>>(x, p_xh, MR * Dc / 2);
    f2h_k<<<(3 * Dc * Dc / 2 + 255) / 256, 256>>>(Wqkv, p_wqkvh, 3 * Dc * Dc / 2);
    f2h_k<<<(Dc * Dc / 2 + 255) / 256, 256>>>(Wo, p_woh, Dc * Dc / 2);
    f2h_k<<<(FFNc * Dc / 2 + 255) / 256, 256>>>(W1, p_w1h, FFNc * Dc / 2);
    f2h_k<<<(Dc * FFNc / 2 + 255) / 256, 256>>>(W2, p_w2h, Dc * FFNc / 2);
    // QKV projection -> fp16
    gemm_proj_k<<<dim3(6, MR / 128), 256, SMEM_128>>>(p_xh, p_wqkvh, bqkv, p_qkvh, nullptr,
                                                      Dc, Dc, 3 * Dc, Dc, 0);
    vt_pack<<<dim3(Tc / 64, Bc * Hc), 256>>>(p_qkvh);
    // scores -> E (fp16) + denominators
    gemm_score_k<<<dim3(Tc / 128, Tc / 128, Bc * Hc), 256, SMEM_128>>>(p_qkvh, mask);
    dinv_k<<<256, 256>>>();
    // PV -> attn fp16
    gemm_pv_k<<<dim3(1, Tc / 128, Bc * Hc), 256, SMEM_64>>>();
    // halting
    colsum_h<<<dim3(4, Bc * Hc, 4), 256>>>();
    halting_k<<<Bc, 256>>>(mask, halt);
    // out-proj + LN1
    gemm_proj_k<<<dim3(2, MR / 128), 256, SMEM_128>>>(p_attnh, p_woh, bo, nullptr, p_proj,
                                                      Dc, Dc, Dc, Dc, 0);
    addln_k<<<MR / 8, 256>>>(x, p_proj, g1, be1, p_h, p_hh);
    // FFN
    gemm_proj_k<<<dim3(8, MR / 128), 256, SMEM_128>>>(p_hh, p_w1h, b1, p_fh, nullptr,
                                                      Dc, Dc, FFNc, Dc, 1);
    gemm_proj_k<<<dim3(2, MR / 128), 256, SMEM_128>>>(p_fh, p_w2h, b2, nullptr, p_ffn,
                                                      FFNc, FFNc, Dc, FFNc, 0);
    addln_k<<<MR / 8, 256>>>(p_h, p_ffn, g2, be2, out, nullptr);
}

// round 4
// speedup vs baseline: 5.6789x; 1.2980x over previous
#include <cuda_runtime.h>
#include <cuda_fp16.h>
#include <cstdint>
#include <cstddef>

#define Bc 8
#define Tc 2048
#define Dc 256
#define Hc 4
#define FFNc 1024

// ---------------- scratch (static device arrays) ----------------
__device__ __half g_xh[(size_t)Bc * Tc * Dc];
__device__ __half g_qkvh[(size_t)Bc * Tc * 3 * Dc];
__device__ __half g_vth[(size_t)Bc * Hc * 64 * Tc];     // V^T fp16 [bh][d][k]
__device__ __half g_attnh[(size_t)Bc * Tc * Dc];
__device__ __half g_hh[(size_t)Bc * Tc * Dc];
__device__ __half g_fh[(size_t)Bc * Tc * FFNc];
__device__ __half g_wqkvh[3 * Dc * Dc];
__device__ __half g_woh[Dc * Dc];
__device__ __half g_w1h[FFNc * Dc];
__device__ __half g_w2h[Dc * FFNc];
__device__ float g_Dinv[Bc * Hc * Tc];
__device__ float g_proj[(size_t)Bc * Tc * Dc];
__device__ float g_h[(size_t)Bc * Tc * Dc];
__device__ float g_ffn[(size_t)Bc * Tc * Dc];
__device__ float g_hraw[Bc * Tc];

// ---------------- helpers ----------------
__device__ __forceinline__ uint32_t s2u(const void* p) {
    uint32_t a;
    asm("{ .reg .u64 t; cvta.to.shared.u64 t, %1; cvt.u32.u64 %0, t; }" : "=r"(a) : "l"(p));
    return a;
}
#define CP_ASYNC16(dst, src) \
    asm volatile("cp.async.cg.shared.global [%0], [%1], 16;" :: "r"(dst), "l"(src))

__device__ __forceinline__ void ldm_x4(uint32_t* r, uint32_t addr) {
    asm volatile("ldmatrix.sync.aligned.m8n8.x4.shared.b16 {%0,%1,%2,%3}, [%4];"
                 : "=r"(r[0]), "=r"(r[1]), "=r"(r[2]), "=r"(r[3]) : "r"(addr));
}
__device__ __forceinline__ void mma16816(float* c, const uint32_t* a, const uint32_t* b) {
    asm volatile("mma.sync.aligned.m16n8k16.row.col.f32.f16.f16.f32 "
                 "{%0,%1,%2,%3}, {%4,%5,%6,%7}, {%8,%9}, {%0,%1,%2,%3};"
                 : "+f"(c[0]), "+f"(c[1]), "+f"(c[2]), "+f"(c[3])
                 : "r"(a[0]), "r"(a[1]), "r"(a[2]), "r"(a[3]), "r"(b[0]), "r"(b[1]));
}

// S-tile: acc[4][2][4] += A(128x64 smem, swz rows of 128B) @ B(64x64 smem)^T
__device__ __forceinline__ void stile64(uint32_t As, uint32_t Bs, float (&acc)[4][2][4],
                                        int lane, int wm, int wn) {
#pragma unroll
    for (int ks = 0; ks < 4; ++ks) {
        const int ck = ks * 2 + (lane >> 4);
        uint32_t af[4][4];
#pragma unroll
        for (int mt = 0; mt < 4; ++mt) {
            int m = wm + mt * 16 + (lane & 15);
            ldm_x4(af[mt], As + m * 128 + ((ck ^ (m & 7)) << 4));
        }
        uint32_t bf[2][2];
        {
            uint32_t r4[4];
            int n = wn + (lane & 15);
            ldm_x4(r4, Bs + n * 128 + ((ck ^ (n & 7)) << 4));
            bf[0][0] = r4[0]; bf[0][1] = r4[2];
            bf[1][0] = r4[1]; bf[1][1] = r4[3];
        }
#pragma unroll
        for (int mt = 0; mt < 4; ++mt)
#pragma unroll
            for (int nt = 0; nt < 2; ++nt) mma16816(acc[mt][nt], af[mt], bf[nt]);
    }
}

// ---------------- fused attention pass 1: S -> e -> d, PV (no E spill) ----------------
// grid (16 q-tiles, 32 bh), 256 threads.
__global__ __launch_bounds__(256) void attn_fused_k(const __half* __restrict__ qkvh,
                                                    const float* __restrict__ mask) {
    extern __shared__ char sm[];
    const uint32_t S0 = s2u(sm);
    const uint32_t Qs = S0, Ks = S0 + 16384, Vs = S0 + 32768, Es = S0 + 49152;
    float* msk = (float*)(sm + 65536);       // 2048
    float* dsum = (float*)(sm + 73728);      // 128
    float* dinv_sm = (float*)(sm + 74240);   // 128
    const int tid = threadIdx.x, lane = tid & 31, wid = tid >> 5;
    const int bh = blockIdx.y, b = bh >> 2, h = bh & 3;
    const int m0 = blockIdx.x * 128;
    const int wm = (wid >> 2) * 64, wn = (wid & 3) * 16;

    for (int i = tid; i < Tc; i += 256) msk[i] = (mask[b * Tc + i] > 0.5f) ? 0.f : 1.f;
    if (tid < 128) dsum[tid] = 0.f;

    {   // Q tile
        const __half* q0 = qkvh + ((size_t)(b * Tc + m0)) * 768 + h * 64;
#pragma unroll
        for (int i = 0; i < 4; ++i) {
            int ch = i * 256 + tid, r = ch >> 3, c = ch & 7;
            CP_ASYNC16(Qs + r * 128 + ((c ^ (r & 7)) << 4), q0 + (size_t)r * 768 + c * 8);
        }
    }
    auto loadKV = [&](int kt, int buf) {
        const int k0 = kt * 64;
        const __half* kg = qkvh + ((size_t)(b * Tc + k0)) * 768 + 256 + h * 64;
        const __half* vg = g_vth + (size_t)bh * 64 * Tc + k0;
#pragma unroll
        for (int i = 0; i < 2; ++i) {
            int ch = i * 256 + tid, r = ch >> 3, c = ch & 7;
            uint32_t off = r * 128 + ((c ^ (r & 7)) << 4);
            CP_ASYNC16(Ks + buf * 8192 + off, kg + (size_t)r * 768 + c * 8);
            CP_ASYNC16(Vs + buf * 8192 + off, vg + (size_t)r * Tc + c * 8);
        }
    };
    loadKV(0, 0);
    asm volatile("cp.async.commit_group;");

    float pacc[4][2][4];
    float dacc[4][2];
#pragma unroll
    for (int mt = 0; mt < 4; ++mt) {
        dacc[mt][0] = dacc[mt][1] = 0.f;
#pragma unroll
        for (int nt = 0; nt < 2; ++nt)
#pragma unroll
            for (int i = 0; i < 4; ++i) pacc[mt][nt][i] = 0.f;
    }

    for (int kt = 0; kt < 32; ++kt) {
        const int buf = kt & 1;
        asm volatile("cp.async.wait_group 0;");
        __syncthreads();
        float sacc[4][2][4];
#pragma unroll
        for (int mt = 0; mt < 4; ++mt)
#pragma unroll
            for (int nt = 0; nt < 2; ++nt)
#pragma unroll
                for (int i = 0; i < 4; ++i) sacc[mt][nt][i] = 0.f;
        stile64(Qs, Ks + buf * 8192, sacc, lane, wm, wn);
        if (kt + 1 < 32) {
            loadKV(kt + 1, buf ^ 1);
            asm volatile("cp.async.commit_group;");
        }
        const int k0 = kt * 64;
#pragma unroll
        for (int mt = 0; mt < 4; ++mt) {
            const int r = wm + mt * 16 + (lane >> 2);
#pragma unroll
            for (int nt = 0; nt < 2; ++nt) {
                const int c = wn + nt * 8 + 2 * (lane & 3);
                const float mu0 = msk[k0 + c], mu1 = msk[k0 + c + 1];
                float e0 = __expf(sacc[mt][nt][0] * 0.125f) * mu0;
                float e1 = __expf(sacc[mt][nt][1] * 0.125f) * mu1;
                float e2 = __expf(sacc[mt][nt][2] * 0.125f) * mu0;
                float e3 = __expf(sacc[mt][nt][3] * 0.125f) * mu1;
                dacc[mt][0] += e0 + e1;
                dacc[mt][1] += e2 + e3;
                const uint32_t chunk = (uint32_t)(c >> 3);
                const uint32_t rem = (uint32_t)((c * 2) & 15);
                uint32_t a0 = Es + r * 128 + (((chunk) ^ (r & 7)) << 4) + rem;
                uint32_t a1 = Es + (r + 8) * 128 + (((chunk) ^ ((r + 8) & 7)) << 4) + rem;
                __half2 h0 = __floats2half2_rn(e0, e1);
                __half2 h1 = __floats2half2_rn(e2, e3);
                asm volatile("st.shared.b32 [%0], %1;" :: "r"(a0), "r"(*(uint32_t*)&h0));
                asm volatile("st.shared.b32 [%0], %1;" :: "r"(a1), "r"(*(uint32_t*)&h1));
            }
        }
        __syncthreads();
        stile64(Es, Vs + buf * 8192, pacc, lane, wm, wn);
        __syncthreads();
    }

    // reduce denominators
#pragma unroll
    for (int mt = 0; mt < 4; ++mt) {
        float d0 = dacc[mt][0], d1 = dacc[mt][1];
        d0 += __shfl_xor_sync(~0u, d0, 1); d0 += __shfl_xor_sync(~0u, d0, 2);
        d1 += __shfl_xor_sync(~0u, d1, 1); d1 += __shfl_xor_sync(~0u, d1, 2);
        if ((lane & 3) == 0) {
            atomicAdd(&dsum[wm + mt * 16 + (lane >> 2)], d0);
            atomicAdd(&dsum[wm + mt * 16 + (lane >> 2) + 8], d1);
        }
    }
    __syncthreads();
    if (tid < 128) {
        float dv = 1.f / dsum[tid];
        dinv_sm[tid] = dv;
        g_Dinv[bh * Tc + m0 + tid] = dv;
    }
    __syncthreads();
#pragma unroll
    for (int mt = 0; mt < 4; ++mt) {
        const int r = wm + mt * 16 + (lane >> 2);
        const float d0 = dinv_sm[r], d1 = dinv_sm[r + 8];
#pragma unroll
        for (int nt = 0; nt < 2; ++nt) {
            const int c = wn + nt * 8 + 2 * (lane & 3);
            *(__half2*)(g_attnh + (size_t)(b * Tc + m0 + r) * Dc + h * 64 + c) =
                __floats2half2_rn(pacc[mt][nt][0] * d0, pacc[mt][nt][1] * d0);
            *(__half2*)(g_attnh + (size_t)(b * Tc + m0 + r + 8) * Dc + h * 64 + c) =
                __floats2half2_rn(pacc[mt][nt][2] * d1, pacc[mt][nt][3] * d1);
        }
    }
}

// ---------------- pass 2: recompute e, weight by Dinv, column sums ----------------
__global__ __launch_bounds__(256) void colsum_rec_k(const __half* __restrict__ qkvh,
                                                    const float* __restrict__ mask) {
    extern __shared__ char sm[];
    const uint32_t S0 = s2u(sm);
    const uint32_t Qs = S0, Ks = S0 + 16384;
    float* msk = (float*)(sm + 32768);   // 2048
    const int tid = threadIdx.x, lane = tid & 31, wid = tid >> 5;
    const int bh = blockIdx.y, b = bh >> 2, h = bh & 3;
    const int m0 = blockIdx.x * 128;
    const int wm = (wid >> 2) * 64, wn = (wid & 3) * 16;

    for (int i = tid; i < Tc; i += 256) msk[i] = (mask[b * Tc + i] > 0.5f) ? 0.f : 1.f;
    {
        const __half* q0 = qkvh + ((size_t)(b * Tc + m0)) * 768 + h * 64;
#pragma unroll
        for (int i = 0; i < 4; ++i) {
            int ch = i * 256 + tid, r = ch >> 3, c = ch & 7;
            CP_ASYNC16(Qs + r * 128 + ((c ^ (r & 7)) << 4), q0 + (size_t)r * 768 + c * 8);
        }
    }
    auto loadK = [&](int kt, int buf) {
        const __half* kg = qkvh + ((size_t)(b * Tc + kt * 64)) * 768 + 256 + h * 64;
#pragma unroll
        for (int i = 0; i < 2; ++i) {
            int ch = i * 256 + tid, r = ch >> 3, c = ch & 7;
            CP_ASYNC16(Ks + buf * 8192 + r * 128 + ((c ^ (r & 7)) << 4), kg + (size_t)r * 768 + c * 8);
        }
    };
    loadK(0, 0);
    asm volatile("cp.async.commit_group;");

    float dr0[4], dr1[4];
#pragma unroll
    for (int mt = 0; mt < 4; ++mt) {
        const int r = wm + mt * 16 + (lane >> 2);
        dr0[mt] = g_Dinv[bh * Tc + m0 + r];
        dr1[mt] = g_Dinv[bh * Tc + m0 + r + 8];
    }

    for (int kt = 0; kt < 32; ++kt) {
        const int buf = kt & 1;
        asm volatile("cp.async.wait_group 0;");
        __syncthreads();
        float sacc[4][2][4];
#pragma unroll
        for (int mt = 0; mt < 4; ++mt)
#pragma unroll
            for (int nt = 0; nt < 2; ++nt)
#pragma unroll
                for (int i = 0; i < 4; ++i) sacc[mt][nt][i] = 0.f;
        stile64(Qs, Ks + buf * 8192, sacc, lane, wm, wn);
        if (kt + 1 < 32) {
            loadK(kt + 1, buf ^ 1);
            asm volatile("cp.async.commit_group;");
        }
        const int k0 = kt * 64;
        float cp[2][2] = {{0.f, 0.f}, {0.f, 0.f}};
#pragma unroll
        for (int mt = 0; mt < 4; ++mt) {
#pragma unroll
            for (int nt = 0; nt < 2; ++nt) {
                const int c = wn + nt * 8 + 2 * (lane & 3);
                const float mu0 = msk[k0 + c], mu1 = msk[k0 + c + 1];
                cp[nt][0] += __expf(sacc[mt][nt][0] * 0.125f) * mu0 * dr0[mt]
                           + __expf(sacc[mt][nt][2] * 0.125f) * mu0 * dr1[mt];
                cp[nt][1] += __expf(sacc[mt][nt][1] * 0.125f) * mu1 * dr0[mt]
                           + __expf(sacc[mt][nt][3] * 0.125f) * mu1 * dr1[mt];
            }
        }
#pragma unroll
        for (int nt = 0; nt < 2; ++nt)
#pragma unroll
            for (int j = 0; j < 2; ++j) {
                float v = cp[nt][j];
                v += __shfl_xor_sync(~0u, v, 4);
                v += __shfl_xor_sync(~0u, v, 8);
                v += __shfl_xor_sync(~0u, v, 16);
                if (lane < 4) {
                    const int c = wn + nt * 8 + 2 * lane + j;
                    atomicAdd(&g_hraw[b * Tc + k0 + c], 0.25f * v);
                }
            }
        __syncthreads();
    }
}

// ---------------- fp16 mma.sync GEMM core (projections) ----------------
template <int BN>
__device__ __forceinline__ void gemm_core(const __half* __restrict__ Ag, int lda,
                                          const __half* __restrict__ Bg, int ldb,
                                          int K, int m0, int n0,
                                          float (&acc)[4][BN / 32][4]) {
    extern __shared__ char smem_raw[];
    constexpr int NT8 = BN / 32;
    const int tid = threadIdx.x, lane = tid & 31, wid = tid >> 5;
    const int wm = (wid >> 2) * 64;
    const int wn = (wid & 3) * (BN / 4);
    const uint32_t sA = s2u(smem_raw);
    const uint32_t sB = sA + 2 * 128 * 128;
    const int NKT = K >> 6;

#pragma unroll
    for (int mt = 0; mt < 4; ++mt)
#pragma unroll
        for (int nt = 0; nt < NT8; ++nt)
#pragma unroll
            for (int i = 0; i < 4; ++i) acc[mt][nt][i] = 0.f;

    auto loadA = [&](int kt, int buf) {
        const __half* s0 = Ag + (size_t)m0 * lda + kt * 64;
        uint32_t d0 = sA + buf * (128 * 128);
#pragma unroll
        for (int i = 0; i < 4; ++i) {
            int ch = i * 256 + tid;
            int r = ch >> 3, c = ch & 7;
            CP_ASYNC16(d0 + r * 128 + ((c ^ (r & 7)) << 4), s0 + (size_t)r * lda + c * 8);
        }
    };
    auto loadB = [&](int kt, int buf) {
        const __half* s0 = Bg + (size_t)n0 * ldb + kt * 64;
        uint32_t d0 = sB + buf * (BN * 128);
#pragma unroll
        for (int i = 0; i < NT8; ++i) {
            int ch = i * 256 + tid;
            int r = ch >> 3, c = ch & 7;
            CP_ASYNC16(d0 + r * 128 + ((c ^ (r & 7)) << 4), s0 + (size_t)r * ldb + c * 8);
        }
    };

    loadA(0, 0); loadB(0, 0);
    asm volatile("cp.async.commit_group;");

    for (int t = 0; t < NKT; ++t) {
        const int buf = t & 1;
        if (t + 1 < NKT) {
            loadA(t + 1, buf ^ 1); loadB(t + 1, buf ^ 1);
            asm volatile("cp.async.commit_group;");
            asm volatile("cp.async.wait_group 1;");
        } else {
            asm volatile("cp.async.wait_group 0;");
        }
        __syncthreads();
        const uint32_t cA = sA + buf * (128 * 128);
        const uint32_t cB = sB + buf * (BN * 128);
#pragma unroll
        for (int ks = 0; ks < 4; ++ks) {
            uint32_t af[4][4];
#pragma unroll
            for (int mt = 0; mt < 4; ++mt) {
                int m = wm + mt * 16 + (lane & 15);
                int ck = ks * 2 + (lane >> 4);
                ldm_x4(af[mt], cA + m * 128 + ((ck ^ (m & 7)) << 4));
            }
            uint32_t bf[NT8][2];
#pragma unroll
            for (int g = 0; g < NT8 / 2; ++g) {
                uint32_t r4[4];
                int n = wn + g * 16 + (lane & 15);
                int ck = ks * 2 + (lane >> 4);
                ldm_x4(r4, cB + n * 128 + ((ck ^ (n & 7)) << 4));
                bf[2 * g][0] = r4[0]; bf[2 * g][1] = r4[2];
                bf[2 * g + 1][0] = r4[1]; bf[2 * g + 1][1] = r4[3];
            }
#pragma unroll
            for (int mt = 0; mt < 4; ++mt)
#pragma unroll
                for (int nt = 0; nt < NT8; ++nt) mma16816(acc[mt][nt], af[mt], bf[nt]);
        }
        __syncthreads();
    }
}

__global__ __launch_bounds__(256) void gemm_proj_k(const __half* __restrict__ A,
                                                   const __half* __restrict__ Bw,
                                                   const float* __restrict__ bias,
                                                   __half* __restrict__ Ch, float* __restrict__ Cf,
                                                   int lda, int ldb, int ldc, int K, int relu) {
    float acc[4][4][4];
    const int m0 = blockIdx.y * 128, n0 = blockIdx.x * 128;
    gemm_core<128>(A, lda, Bw, ldb, K, m0, n0, acc);
    const int lane = threadIdx.x & 31, wid = threadIdx.x >> 5;
    const int wm = (wid >> 2) * 64, wn = (wid & 3) * 32;
#pragma unroll
    for (int mt = 0; mt < 4; ++mt) {
        int r = m0 + wm + mt * 16 + (lane >> 2);
#pragma unroll
        for (int nt = 0; nt < 4; ++nt) {
            int col = n0 + wn + nt * 8 + 2 * (lane & 3);
            float bx = __ldg(bias + col), by = __ldg(bias + col + 1);
            float v0 = acc[mt][nt][0] + bx, v1 = acc[mt][nt][1] + by;
            float v2 = acc[mt][nt][2] + bx, v3 = acc[mt][nt][3] + by;
            if (relu) {
                v0 = fmaxf(v0, 0.f); v1 = fmaxf(v1, 0.f);
                v2 = fmaxf(v2, 0.f); v3 = fmaxf(v3, 0.f);
            }
            if (Ch) {
                *(__half2*)(Ch + (size_t)r * ldc + col) = __floats2half2_rn(v0, v1);
                *(__half2*)(Ch + (size_t)(r + 8) * ldc + col) = __floats2half2_rn(v2, v3);
            }
            if (Cf) {
                *(float2*)(Cf + (size_t)r * ldc + col) = make_float2(v0, v1);
                *(float2*)(Cf + (size_t)(r + 8) * ldc + col) = make_float2(v2, v3);
            }
        }
    }
}

// ---------------- V transpose ----------------
__global__ __launch_bounds__(256) void vt_pack(const __half* __restrict__ qkvh) {
    __shared__ __half tile[64][72];
    const int bh = blockIdx.y, b = bh >> 2, h = bh & 3;
    const int k0 = blockIdx.x * 64;
    const int t = threadIdx.x;
#pragma unroll
    for (int i = 0; i < 16; ++i) {
        int idx = t + i * 256, kk = idx >> 6, d = idx & 63;
        tile[kk][d] = qkvh[(size_t)(b * Tc + k0 + kk) * 768 + 512 + h * 64 + d];
    }
    __syncthreads();
#pragma unroll
    for (int i = 0; i < 16; ++i) {
        int idx = t + i * 256, d = idx >> 6, kk = idx & 63;
        g_vth[(size_t)bh * 64 * Tc + (size_t)d * Tc + k0 + kk] = tile[kk][d];
    }
}

// ---------------- small kernels ----------------
__global__ void f2h_k(const float* __restrict__ s, __half* __restrict__ d, int n2) {
    int i = blockIdx.x * 256 + threadIdx.x;
    if (i < n2) {
        float2 v = ((const float2*)s)[i];
        ((__half2*)d)[i] = __floats2half2_rn(v.x, v.y);
    }
}
__global__ void zero_k() {
    int i = blockIdx.x * 256 + threadIdx.x;
    if (i < Bc * Tc) g_hraw[i] = 0.f;
}

__global__ __launch_bounds__(256) void halting_k(const float* __restrict__ mask, float* __restrict__ out) {
    const int b = blockIdx.x;
    const int t = threadIdx.x;
    __shared__ float es[Tc];
    __shared__ float redm[8], reds[8];
    float lmax = -3.4e38f;
    for (int k = t; k < Tc; k += 256) {
        float v = g_hraw[b * Tc + k] + mask[b * Tc + k] * (-1e10f);
        es[k] = v;
        lmax = fmaxf(lmax, v);
    }
#pragma unroll
    for (int o = 16; o; o >>= 1) lmax = fmaxf(lmax, __shfl_xor_sync(~0u, lmax, o));
    if ((t & 31) == 0) redm[t >> 5] = lmax;
    __syncthreads();
    float bmax = redm[0];
#pragma unroll
    for (int j = 1; j < 8; ++j) bmax = fmaxf(bmax, redm[j]);
    float lsum = 0.f;
    for (int k = t; k < Tc; k += 256) {
        float e = __expf(es[k] - bmax);
        es[k] = e;
        lsum += e;
    }
#pragma unroll
    for (int o = 16; o; o >>= 1) lsum += __shfl_xor_sync(~0u, lsum, o);
    if ((t & 31) == 0) reds[t >> 5] = lsum;
    __syncthreads();
    float bsum = 0.f;
#pragma unroll
    for (int j = 0; j < 8; ++j) bsum += reds[j];
    const float inv = 1.f / bsum;
    for (int k = t; k < Tc; k += 256) out[b * Tc + k] = es[k] * inv;
}

__global__ __launch_bounds__(256) void addln_k(const float* __restrict__ x, const float* __restrict__ y,
                                               const float* __restrict__ g, const float* __restrict__ be,
                                               float* __restrict__ outf, __half* __restrict__ outh) {
    const int warp = threadIdx.x >> 5, lane = threadIdx.x & 31;
    const size_t row = (size_t)blockIdx.x * 8 + warp;
    const float* xr = x + row * Dc;
    const float* yr = y + row * Dc;
    float v[8];
    float s = 0.f, sq = 0.f;
#pragma unroll
    for (int i = 0; i < 8; ++i) {
        float z = xr[lane + 32 * i] + yr[lane + 32 * i];
        v[i] = z; s += z; sq += z * z;
    }
#pragma unroll
    for (int o = 16; o; o >>= 1) { s += __shfl_xor_sync(~0u, s, o); sq += __shfl_xor_sync(~0u, sq, o); }
    const float mean = s * (1.f / Dc);
    const float var = sq * (1.f / Dc) - mean * mean;
    const float rstd = rsqrtf(var + 1e-5f);
#pragma unroll
    for (int i = 0; i < 8; ++i) {
        int c = lane + 32 * i;
        float o = (v[i] - mean) * rstd * g[c] + be[c];
        if (outf) outf[row * Dc + c] = o;
        if (outh) outh[row * Dc + c] = __float2half(o);
    }
}

// =====================================================================
extern "C" void kernel_launch(void* const* d_in, const int* in_sizes, int n_in,
                              void* d_out, int out_size) {
    (void)in_sizes; (void)n_in; (void)out_size;
    const float* x    = (const float*)d_in[0];
    const float* mask = (const float*)d_in[1];
    const float* Wqkv = (const float*)d_in[2];
    const float* bqkv = (const float*)d_in[3];
    const float* Wo   = (const float*)d_in[4];
    const float* bo   = (const float*)d_in[5];
    const float* W1   = (const float*)d_in[6];
    const float* b1   = (const float*)d_in[7];
    const float* W2   = (const float*)d_in[8];
    const float* b2   = (const float*)d_in[9];
    const float* g1   = (const float*)d_in[10];
    const float* be1  = (const float*)d_in[11];
    const float* g2   = (const float*)d_in[12];
    const float* be2  = (const float*)d_in[13];
    float* out  = (float*)d_out;
    float* halt = out + (size_t)Bc * Tc * Dc;

    __half *p_xh, *p_qkvh, *p_attnh, *p_hh, *p_fh, *p_wqkvh, *p_woh, *p_w1h, *p_w2h;
    float *p_proj, *p_h, *p_ffn;
    cudaGetSymbolAddress((void**)&p_xh, g_xh);
    cudaGetSymbolAddress((void**)&p_qkvh, g_qkvh);
    cudaGetSymbolAddress((void**)&p_attnh, g_attnh);
    cudaGetSymbolAddress((void**)&p_hh, g_hh);
    cudaGetSymbolAddress((void**)&p_fh, g_fh);
    cudaGetSymbolAddress((void**)&p_wqkvh, g_wqkvh);
    cudaGetSymbolAddress((void**)&p_woh, g_woh);
    cudaGetSymbolAddress((void**)&p_w1h, g_w1h);
    cudaGetSymbolAddress((void**)&p_w2h, g_w2h);
    cudaGetSymbolAddress((void**)&p_proj, g_proj);
    cudaGetSymbolAddress((void**)&p_h, g_h);
    cudaGetSymbolAddress((void**)&p_ffn, g_ffn);

    const int SMEM_128 = 65536;
    const int SMEM_AT  = 74752;   // Q16K + K16K + V16K + E16K + mask8K + dsum/dinv
    const int SMEM_CS  = 40960;   // Q16K + K16K + mask8K
    cudaFuncSetAttribute(gemm_proj_k,  cudaFuncAttributeMaxDynamicSharedMemorySize, SMEM_128);
    cudaFuncSetAttribute(attn_fused_k, cudaFuncAttributeMaxDynamicSharedMemorySize, SMEM_AT);
    cudaFuncSetAttribute(colsum_rec_k, cudaFuncAttributeMaxDynamicSharedMemorySize, SMEM_CS);

    const int MR = Bc * Tc;  // 16384

    zero_k<<<64, 256>>>();
    // fp32 -> fp16 packing
    f2h_k<<<(MR * Dc / 2 + 255) / 256, 256>>>(x, p_xh, MR * Dc / 2);
    f2h_k<<<(3 * Dc * Dc / 2 + 255) / 256, 256>>>(Wqkv, p_wqkvh, 3 * Dc * Dc / 2);
    f2h_k<<<(Dc * Dc / 2 + 255) / 256, 256>>>(Wo, p_woh, Dc * Dc / 2);
    f2h_k<<<(FFNc * Dc / 2 + 255) / 256, 256>>>(W1, p_w1h, FFNc * Dc / 2);
    f2h_k<<<(Dc * FFNc / 2 + 255) / 256, 256>>>(W2, p_w2h, Dc * FFNc / 2);
    // QKV projection -> fp16
    gemm_proj_k<<<dim3(6, MR / 128), 256, SMEM_128>>>(p_xh, p_wqkvh, bqkv, p_qkvh, nullptr,
                                                      Dc, Dc, 3 * Dc, Dc, 0);
    vt_pack<<<dim3(Tc / 64, Bc * Hc), 256>>>(p_qkvh);
    // fused attention (pass 1): attn + Dinv, no E spill
    attn_fused_k<<<dim3(Tc / 128, Bc * Hc), 256, SMEM_AT>>>(p_qkvh, mask);
    // pass 2: recompute for halting column sums
    colsum_rec_k<<<dim3(Tc / 128, Bc * Hc), 256, SMEM_CS>>>(p_qkvh, mask);
    halting_k<<<Bc, 256>>>(mask, halt);
    // out-proj + LN1
    gemm_proj_k<<<dim3(2, MR / 128), 256, SMEM_128>>>(p_attnh, p_woh, bo, nullptr, p_proj,
                                                      Dc, Dc, Dc, Dc, 0);
    addln_k<<<MR / 8, 256>>>(x, p_proj, g1, be1, p_h, p_hh);
    // FFN
    gemm_proj_k<<<dim3(8, MR / 128), 256, SMEM_128>>>(p_hh, p_w1h, b1, p_fh, nullptr,
                                                      Dc, Dc, FFNc, Dc, 1);
    gemm_proj_k<<<dim3(2, MR / 128), 256, SMEM_128>>>(p_fh, p_w2h, b2, nullptr, p_ffn,
                                                      FFNc, FFNc, Dc, FFNc, 0);
    addln_k<<<MR / 8, 256>>>(p_h, p_ffn, g2, be2, out, nullptr);
}

// round 5
// speedup vs baseline: 5.7055x; 1.0047x over previous
#include <cuda_runtime.h>
#include <cuda_fp16.h>
#include <cstdint>
#include <cstddef>

#define Bc 8
#define Tc 2048
#define Dc 256
#define Hc 4
#define FFNc 1024

// ---------------- scratch (static device arrays) ----------------
__device__ __half g_xh[(size_t)Bc * Tc * Dc];
__device__ __half g_qkvh[(size_t)Bc * Tc * 3 * Dc];
__device__ __half g_vth[(size_t)Bc * Hc * 64 * Tc];     // V^T fp16 [bh][d][k]
__device__ __half g_attnh[(size_t)Bc * Tc * Dc];
__device__ __half g_hh[(size_t)Bc * Tc * Dc];
__device__ __half g_fh[(size_t)Bc * Tc * FFNc];
__device__ __half g_wqkvh[3 * Dc * Dc];
__device__ __half g_woh[Dc * Dc];
__device__ __half g_w1h[FFNc * Dc];
__device__ __half g_w2h[Dc * FFNc];
__device__ float g_h[(size_t)Bc * Tc * Dc];
__device__ float g_hraw[Bc * Tc];

// ---------------- helpers ----------------
__device__ __forceinline__ uint32_t s2u(const void* p) {
    uint32_t a;
    asm("{ .reg .u64 t; cvta.to.shared.u64 t, %1; cvt.u32.u64 %0, t; }" : "=r"(a) : "l"(p));
    return a;
}
#define CP_ASYNC16(dst, src) \
    asm volatile("cp.async.cg.shared.global [%0], [%1], 16;" :: "r"(dst), "l"(src))

__device__ __forceinline__ void ldm_x4(uint32_t* r, uint32_t addr) {
    asm volatile("ldmatrix.sync.aligned.m8n8.x4.shared.b16 {%0,%1,%2,%3}, [%4];"
                 : "=r"(r[0]), "=r"(r[1]), "=r"(r[2]), "=r"(r[3]) : "r"(addr));
}
__device__ __forceinline__ void mma16816(float* c, const uint32_t* a, const uint32_t* b) {
    asm volatile("mma.sync.aligned.m16n8k16.row.col.f32.f16.f16.f32 "
                 "{%0,%1,%2,%3}, {%4,%5,%6,%7}, {%8,%9}, {%0,%1,%2,%3};"
                 : "+f"(c[0]), "+f"(c[1]), "+f"(c[2]), "+f"(c[3])
                 : "r"(a[0]), "r"(a[1]), "r"(a[2]), "r"(a[3]), "r"(b[0]), "r"(b[1]));
}

// S-tile: acc[4][2][4] += A(128x64 smem, swz rows of 128B) @ B(64x64 smem)^T
__device__ __forceinline__ void stile64(uint32_t As, uint32_t Bs, float (&acc)[4][2][4],
                                        int lane, int wm, int wn) {
#pragma unroll
    for (int ks = 0; ks < 4; ++ks) {
        const int ck = ks * 2 + (lane >> 4);
        uint32_t af[4][4];
#pragma unroll
        for (int mt = 0; mt < 4; ++mt) {
            int m = wm + mt * 16 + (lane & 15);
            ldm_x4(af[mt], As + m * 128 + ((ck ^ (m & 7)) << 4));
        }
        uint32_t bf[2][2];
        {
            uint32_t r4[4];
            int n = wn + (lane & 15);
            ldm_x4(r4, Bs + n * 128 + ((ck ^ (n & 7)) << 4));
            bf[0][0] = r4[0]; bf[0][1] = r4[2];
            bf[1][0] = r4[1]; bf[1][1] = r4[3];
        }
#pragma unroll
        for (int mt = 0; mt < 4; ++mt)
#pragma unroll
            for (int nt = 0; nt < 2; ++nt) mma16816(acc[mt][nt], af[mt], bf[nt]);
    }
}

// ---------------- merged attention: denominators, then normalized PV + colsum ----------------
// grid (16 q-tiles, 32 bh), 256 threads.
__global__ __launch_bounds__(256) void attn2_k(const __half* __restrict__ qkvh,
                                               const float* __restrict__ mask) {
    extern __shared__ char sm[];
    const uint32_t S0 = s2u(sm);
    const uint32_t Qs = S0, Ks = S0 + 16384, Vs = S0 + 32768, Es = S0 + 49152;
    float* msk = (float*)(sm + 65536);       // 2048 floats (8KB)
    float* dsum = (float*)(sm + 73728);      // 128
    float* dinv_sm = (float*)(sm + 74240);   // 128
    const int tid = threadIdx.x, lane = tid & 31, wid = tid >> 5;
    const int bh = blockIdx.y, b = bh >> 2, h = bh & 3;
    const int m0 = blockIdx.x * 128;
    const int wm = (wid >> 2) * 64, wn = (wid & 3) * 16;

    for (int i = tid; i < Tc; i += 256) msk[i] = (mask[b * Tc + i] > 0.5f) ? 0.f : 1.f;
    if (tid < 128) dsum[tid] = 0.f;

    {   // Q tile (persistent)
        const __half* q0 = qkvh + ((size_t)(b * Tc + m0)) * 768 + h * 64;
#pragma unroll
        for (int i = 0; i < 4; ++i) {
            int ch = i * 256 + tid, r = ch >> 3, c = ch & 7;
            CP_ASYNC16(Qs + r * 128 + ((c ^ (r & 7)) << 4), q0 + (size_t)r * 768 + c * 8);
        }
    }
    auto loadK = [&](int kt, int buf) {
        const __half* kg = qkvh + ((size_t)(b * Tc + kt * 64)) * 768 + 256 + h * 64;
#pragma unroll
        for (int i = 0; i < 2; ++i) {
            int ch = i * 256 + tid, r = ch >> 3, c = ch & 7;
            CP_ASYNC16(Ks + buf * 8192 + r * 128 + ((c ^ (r & 7)) << 4), kg + (size_t)r * 768 + c * 8);
        }
    };
    auto loadKV = [&](int kt, int buf) {
        const int k0 = kt * 64;
        const __half* kg = qkvh + ((size_t)(b * Tc + k0)) * 768 + 256 + h * 64;
        const __half* vg = g_vth + (size_t)bh * 64 * Tc + k0;
#pragma unroll
        for (int i = 0; i < 2; ++i) {
            int ch = i * 256 + tid, r = ch >> 3, c = ch & 7;
            uint32_t off = r * 128 + ((c ^ (r & 7)) << 4);
            CP_ASYNC16(Ks + buf * 8192 + off, kg + (size_t)r * 768 + c * 8);
            CP_ASYNC16(Vs + buf * 8192 + off, vg + (size_t)r * Tc + c * 8);
        }
    };

    // ---- loop A: denominators only ----
    loadK(0, 0);
    asm volatile("cp.async.commit_group;");
    float dacc[4][2];
#pragma unroll
    for (int mt = 0; mt < 4; ++mt) dacc[mt][0] = dacc[mt][1] = 0.f;

    for (int kt = 0; kt < 32; ++kt) {
        const int buf = kt & 1;
        asm volatile("cp.async.wait_group 0;");
        __syncthreads();
        float sacc[4][2][4];
#pragma unroll
        for (int mt = 0; mt < 4; ++mt)
#pragma unroll
            for (int nt = 0; nt < 2; ++nt)
#pragma unroll
                for (int i = 0; i < 4; ++i) sacc[mt][nt][i] = 0.f;
        stile64(Qs, Ks + buf * 8192, sacc, lane, wm, wn);
        if (kt + 1 < 32) {
            loadK(kt + 1, buf ^ 1);
            asm volatile("cp.async.commit_group;");
        }
        const int k0 = kt * 64;
#pragma unroll
        for (int mt = 0; mt < 4; ++mt)
#pragma unroll
            for (int nt = 0; nt < 2; ++nt) {
                const int c = wn + nt * 8 + 2 * (lane & 3);
                const float mu0 = msk[k0 + c], mu1 = msk[k0 + c + 1];
                dacc[mt][0] += __expf(sacc[mt][nt][0] * 0.125f) * mu0
                             + __expf(sacc[mt][nt][1] * 0.125f) * mu1;
                dacc[mt][1] += __expf(sacc[mt][nt][2] * 0.125f) * mu0
                             + __expf(sacc[mt][nt][3] * 0.125f) * mu1;
            }
    }
#pragma unroll
    for (int mt = 0; mt < 4; ++mt) {
        float d0 = dacc[mt][0], d1 = dacc[mt][1];
        d0 += __shfl_xor_sync(~0u, d0, 1); d0 += __shfl_xor_sync(~0u, d0, 2);
        d1 += __shfl_xor_sync(~0u, d1, 1); d1 += __shfl_xor_sync(~0u, d1, 2);
        if ((lane & 3) == 0) {
            atomicAdd(&dsum[wm + mt * 16 + (lane >> 2)], d0);
            atomicAdd(&dsum[wm + mt * 16 + (lane >> 2) + 8], d1);
        }
    }
    __syncthreads();
    if (tid < 128) dinv_sm[tid] = 1.f / dsum[tid];
    __syncthreads();

    float dr0[4], dr1[4];
#pragma unroll
    for (int mt = 0; mt < 4; ++mt) {
        const int r = wm + mt * 16 + (lane >> 2);
        dr0[mt] = dinv_sm[r];
        dr1[mt] = dinv_sm[r + 8];
    }

    // ---- loop B: normalized weights -> PV + halting colsum ----
    loadKV(0, 0);
    asm volatile("cp.async.commit_group;");
    float pacc[4][2][4];
#pragma unroll
    for (int mt = 0; mt < 4; ++mt)
#pragma unroll
        for (int nt = 0; nt < 2; ++nt)
#pragma unroll
            for (int i = 0; i < 4; ++i) pacc[mt][nt][i] = 0.f;

    for (int kt = 0; kt < 32; ++kt) {
        const int buf = kt & 1;
        asm volatile("cp.async.wait_group 0;");
        __syncthreads();
        float sacc[4][2][4];
#pragma unroll
        for (int mt = 0; mt < 4; ++mt)
#pragma unroll
            for (int nt = 0; nt < 2; ++nt)
#pragma unroll
                for (int i = 0; i < 4; ++i) sacc[mt][nt][i] = 0.f;
        stile64(Qs, Ks + buf * 8192, sacc, lane, wm, wn);
        if (kt + 1 < 32) {
            loadKV(kt + 1, buf ^ 1);
            asm volatile("cp.async.commit_group;");
        }
        const int k0 = kt * 64;
        float cp[2][2] = {{0.f, 0.f}, {0.f, 0.f}};
#pragma unroll
        for (int mt = 0; mt < 4; ++mt) {
            const int r = wm + mt * 16 + (lane >> 2);
#pragma unroll
            for (int nt = 0; nt < 2; ++nt) {
                const int c = wn + nt * 8 + 2 * (lane & 3);
                const float mu0 = msk[k0 + c], mu1 = msk[k0 + c + 1];
                float w0 = __expf(sacc[mt][nt][0] * 0.125f) * mu0 * dr0[mt];
                float w1 = __expf(sacc[mt][nt][1] * 0.125f) * mu1 * dr0[mt];
                float w2 = __expf(sacc[mt][nt][2] * 0.125f) * mu0 * dr1[mt];
                float w3 = __expf(sacc[mt][nt][3] * 0.125f) * mu1 * dr1[mt];
                cp[nt][0] += w0 + w2;
                cp[nt][1] += w1 + w3;
                const uint32_t chunk = (uint32_t)(c >> 3);
                const uint32_t rem = (uint32_t)((c * 2) & 15);
                uint32_t a0 = Es + r * 128 + ((chunk ^ (r & 7)) << 4) + rem;
                uint32_t a1 = Es + (r + 8) * 128 + ((chunk ^ ((r + 8) & 7)) << 4) + rem;
                __half2 h0 = __floats2half2_rn(w0, w1);
                __half2 h1 = __floats2half2_rn(w2, w3);
                asm volatile("st.shared.b32 [%0], %1;" :: "r"(a0), "r"(*(uint32_t*)&h0));
                asm volatile("st.shared.b32 [%0], %1;" :: "r"(a1), "r"(*(uint32_t*)&h1));
            }
        }
#pragma unroll
        for (int nt = 0; nt < 2; ++nt)
#pragma unroll
            for (int j = 0; j < 2; ++j) {
                float v = cp[nt][j];
                v += __shfl_xor_sync(~0u, v, 4);
                v += __shfl_xor_sync(~0u, v, 8);
                v += __shfl_xor_sync(~0u, v, 16);
                if (lane < 4) {
                    const int c = wn + nt * 8 + 2 * lane + j;
                    atomicAdd(&g_hraw[b * Tc + k0 + c], 0.25f * v);
                }
            }
        __syncthreads();
        stile64(Es, Vs + buf * 8192, pacc, lane, wm, wn);
    }

    // pacc is already normalized
#pragma unroll
    for (int mt = 0; mt < 4; ++mt) {
        const int r = wm + mt * 16 + (lane >> 2);
#pragma unroll
        for (int nt = 0; nt < 2; ++nt) {
            const int c = wn + nt * 8 + 2 * (lane & 3);
            *(__half2*)(g_attnh + (size_t)(b * Tc + m0 + r) * Dc + h * 64 + c) =
                __floats2half2_rn(pacc[mt][nt][0], pacc[mt][nt][1]);
            *(__half2*)(g_attnh + (size_t)(b * Tc + m0 + r + 8) * Dc + h * 64 + c) =
                __floats2half2_rn(pacc[mt][nt][2], pacc[mt][nt][3]);
        }
    }
}

// ---------------- fp16 mma.sync GEMM core (BM=128, BN=128) ----------------
__device__ __forceinline__ void gemm_core128(const __half* __restrict__ Ag, int lda,
                                             const __half* __restrict__ Bg, int ldb,
                                             int K, int m0, int n0,
                                             float (&acc)[4][4][4]) {
    extern __shared__ char smem_raw[];
    const int tid = threadIdx.x, lane = tid & 31, wid = tid >> 5;
    const int wm = (wid >> 2) * 64;
    const int wn = (wid & 3) * 32;
    const uint32_t sA = s2u(smem_raw);
    const uint32_t sB = sA + 2 * 128 * 128;
    const int NKT = K >> 6;

#pragma unroll
    for (int mt = 0; mt < 4; ++mt)
#pragma unroll
        for (int nt = 0; nt < 4; ++nt)
#pragma unroll
            for (int i = 0; i < 4; ++i) acc[mt][nt][i] = 0.f;

    auto loadA = [&](int kt, int buf) {
        const __half* s0 = Ag + (size_t)m0 * lda + kt * 64;
        uint32_t d0 = sA + buf * (128 * 128);
#pragma unroll
        for (int i = 0; i < 4; ++i) {
            int ch = i * 256 + tid, r = ch >> 3, c = ch & 7;
            CP_ASYNC16(d0 + r * 128 + ((c ^ (r & 7)) << 4), s0 + (size_t)r * lda + c * 8);
        }
    };
    auto loadB = [&](int kt, int buf) {
        const __half* s0 = Bg + (size_t)n0 * ldb + kt * 64;
        uint32_t d0 = sB + buf * (128 * 128);
#pragma unroll
        for (int i = 0; i < 4; ++i) {
            int ch = i * 256 + tid, r = ch >> 3, c = ch & 7;
            CP_ASYNC16(d0 + r * 128 + ((c ^ (r & 7)) << 4), s0 + (size_t)r * ldb + c * 8);
        }
    };

    loadA(0, 0); loadB(0, 0);
    asm volatile("cp.async.commit_group;");

    for (int t = 0; t < NKT; ++t) {
        const int buf = t & 1;
        if (t + 1 < NKT) {
            loadA(t + 1, buf ^ 1); loadB(t + 1, buf ^ 1);
            asm volatile("cp.async.commit_group;");
            asm volatile("cp.async.wait_group 1;");
        } else {
            asm volatile("cp.async.wait_group 0;");
        }
        __syncthreads();
        const uint32_t cA = sA + buf * (128 * 128);
        const uint32_t cB = sB + buf * (128 * 128);
#pragma unroll
        for (int ks = 0; ks < 4; ++ks) {
            uint32_t af[4][4];
#pragma unroll
            for (int mt = 0; mt < 4; ++mt) {
                int m = wm + mt * 16 + (lane & 15);
                int ck = ks * 2 + (lane >> 4);
                ldm_x4(af[mt], cA + m * 128 + ((ck ^ (m & 7)) << 4));
            }
            uint32_t bf[4][2];
#pragma unroll
            for (int g = 0; g < 2; ++g) {
                uint32_t r4[4];
                int n = wn + g * 16 + (lane & 15);
                int ck = ks * 2 + (lane >> 4);
                ldm_x4(r4, cB + n * 128 + ((ck ^ (n & 7)) << 4));
                bf[2 * g][0] = r4[0]; bf[2 * g][1] = r4[2];
                bf[2 * g + 1][0] = r4[1]; bf[2 * g + 1][1] = r4[3];
            }
#pragma unroll
            for (int mt = 0; mt < 4; ++mt)
#pragma unroll
                for (int nt = 0; nt < 4; ++nt) mma16816(acc[mt][nt], af[mt], bf[nt]);
        }
        __syncthreads();
    }
}

__global__ __launch_bounds__(256) void gemm_proj_k(const __half* __restrict__ A,
                                                   const __half* __restrict__ Bw,
                                                   const float* __restrict__ bias,
                                                   __half* __restrict__ Ch,
                                                   int lda, int ldb, int ldc, int K, int relu) {
    float acc[4][4][4];
    const int m0 = blockIdx.y * 128, n0 = blockIdx.x * 128;
    gemm_core128(A, lda, Bw, ldb, K, m0, n0, acc);
    const int lane = threadIdx.x & 31, wid = threadIdx.x >> 5;
    const int wm = (wid >> 2) * 64, wn = (wid & 3) * 32;
#pragma unroll
    for (int mt = 0; mt < 4; ++mt) {
        int r = m0 + wm + mt * 16 + (lane >> 2);
#pragma unroll
        for (int nt = 0; nt < 4; ++nt) {
            int col = n0 + wn + nt * 8 + 2 * (lane & 3);
            float bx = __ldg(bias + col), by = __ldg(bias + col + 1);
            float v0 = acc[mt][nt][0] + bx, v1 = acc[mt][nt][1] + by;
            float v2 = acc[mt][nt][2] + bx, v3 = acc[mt][nt][3] + by;
            if (relu) {
                v0 = fmaxf(v0, 0.f); v1 = fmaxf(v1, 0.f);
                v2 = fmaxf(v2, 0.f); v3 = fmaxf(v3, 0.f);
            }
            *(__half2*)(Ch + (size_t)r * ldc + col) = __floats2half2_rn(v0, v1);
            *(__half2*)(Ch + (size_t)(r + 8) * ldc + col) = __floats2half2_rn(v2, v3);
        }
    }
}

// ---------------- GEMM (BM=64, BN=256=N) + bias + residual + LayerNorm ----------------
__global__ __launch_bounds__(256) void gemm_ln_k(const __half* __restrict__ A,
                                                 const __half* __restrict__ Bw,
                                                 const float* __restrict__ bias,
                                                 const float* __restrict__ res,
                                                 const float* __restrict__ gamma,
                                                 const float* __restrict__ beta,
                                                 float* __restrict__ outf,
                                                 __half* __restrict__ outh,
                                                 int lda, int K) {
    extern __shared__ char sm[];
    const uint32_t sA = s2u(sm);               // 2 x 8192
    const uint32_t sB = sA + 16384;            // 2 x 32768
    float* sred = (float*)(sm + 16384 + 65536);
    float* sqred = sred + 64;
    const int tid = threadIdx.x, lane = tid & 31, wid = tid >> 5;
    const int m0 = blockIdx.x * 64;
    const int wm = (wid >> 2) * 32, wn = (wid & 3) * 64;
    const int NKT = K >> 6;

    float acc[2][8][4];
#pragma unroll
    for (int mt = 0; mt < 2; ++mt)
#pragma unroll
        for (int nt = 0; nt < 8; ++nt)
#pragma unroll
            for (int i = 0; i < 4; ++i) acc[mt][nt][i] = 0.f;

    auto loadA = [&](int kt, int buf) {
        const __half* s0 = A + (size_t)m0 * lda + kt * 64;
        uint32_t d0 = sA + buf * 8192;
#pragma unroll
        for (int i = 0; i < 2; ++i) {
            int ch = i * 256 + tid, r = ch >> 3, c = ch & 7;
            CP_ASYNC16(d0 + r * 128 + ((c ^ (r & 7)) << 4), s0 + (size_t)r * lda + c * 8);
        }
    };
    auto loadB = [&](int kt, int buf) {
        const __half* s0 = Bw + kt * 64;
        uint32_t d0 = sB + buf * 32768;
#pragma unroll
        for (int i = 0; i < 8; ++i) {
            int ch = i * 256 + tid, r = ch >> 3, c = ch & 7;
            CP_ASYNC16(d0 + r * 128 + ((c ^ (r & 7)) << 4), s0 + (size_t)r * K + c * 8);
        }
    };

    loadA(0, 0); loadB(0, 0);
    asm volatile("cp.async.commit_group;");

    for (int t = 0; t < NKT; ++t) {
        const int buf = t & 1;
        if (t + 1 < NKT) {
            loadA(t + 1, buf ^ 1); loadB(t + 1, buf ^ 1);
            asm volatile("cp.async.commit_group;");
            asm volatile("cp.async.wait_group 1;");
        } else {
            asm volatile("cp.async.wait_group 0;");
        }
        __syncthreads();
        const uint32_t cA = sA + buf * 8192;
        const uint32_t cB = sB + buf * 32768;
#pragma unroll
        for (int ks = 0; ks < 4; ++ks) {
            const int ck = ks * 2 + (lane >> 4);
            uint32_t af[2][4];
#pragma unroll
            for (int mt = 0; mt < 2; ++mt) {
                int m = wm + mt * 16 + (lane & 15);
                ldm_x4(af[mt], cA + m * 128 + ((ck ^ (m & 7)) << 4));
            }
            uint32_t bf[8][2];
#pragma unroll
            for (int g = 0; g < 4; ++g) {
                uint32_t r4[4];
                int n = wn + g * 16 + (lane & 15);
                ldm_x4(r4, cB + n * 128 + ((ck ^ (n & 7)) << 4));
                bf[2 * g][0] = r4[0]; bf[2 * g][1] = r4[2];
                bf[2 * g + 1][0] = r4[1]; bf[2 * g + 1][1] = r4[3];
            }
#pragma unroll
            for (int mt = 0; mt < 2; ++mt)
#pragma unroll
                for (int nt = 0; nt < 8; ++nt) mma16816(acc[mt][nt], af[mt], bf[nt]);
        }
        __syncthreads();
    }

    // ---- epilogue: bias + residual, LN stats, normalize ----
    if (tid < 64) { sred[tid] = 0.f; sqred[tid] = 0.f; }
    __syncthreads();
#pragma unroll
    for (int mt = 0; mt < 2; ++mt) {
        const int r = wm + mt * 16 + (lane >> 2);
        float s0 = 0.f, sq0 = 0.f, s1 = 0.f, sq1 = 0.f;
#pragma unroll
        for (int nt = 0; nt < 8; ++nt) {
            const int col = wn + nt * 8 + 2 * (lane & 3);
            float bx = __ldg(bias + col), by = __ldg(bias + col + 1);
            float2 r0 = *(const float2*)(res + (size_t)(m0 + r) * Dc + col);
            float2 r1 = *(const float2*)(res + (size_t)(m0 + r + 8) * Dc + col);
            float v0 = acc[mt][nt][0] + bx + r0.x;
            float v1 = acc[mt][nt][1] + by + r0.y;
            float v2 = acc[mt][nt][2] + bx + r1.x;
            float v3 = acc[mt][nt][3] + by + r1.y;
            acc[mt][nt][0] = v0; acc[mt][nt][1] = v1;
            acc[mt][nt][2] = v2; acc[mt][nt][3] = v3;
            s0 += v0 + v1; sq0 += v0 * v0 + v1 * v1;
            s1 += v2 + v3; sq1 += v2 * v2 + v3 * v3;
        }
        s0 += __shfl_xor_sync(~0u, s0, 1); s0 += __shfl_xor_sync(~0u, s0, 2);
        sq0 += __shfl_xor_sync(~0u, sq0, 1); sq0 += __shfl_xor_sync(~0u, sq0, 2);
        s1 += __shfl_xor_sync(~0u, s1, 1); s1 += __shfl_xor_sync(~0u, s1, 2);
        sq1 += __shfl_xor_sync(~0u, sq1, 1); sq1 += __shfl_xor_sync(~0u, sq1, 2);
        if ((lane & 3) == 0) {
            atomicAdd(&sred[r], s0); atomicAdd(&sqred[r], sq0);
            atomicAdd(&sred[r + 8], s1); atomicAdd(&sqred[r + 8], sq1);
        }
    }
    __syncthreads();
#pragma unroll
    for (int mt = 0; mt < 2; ++mt) {
        const int r = wm + mt * 16 + (lane >> 2);
        const float mean0 = sred[r] * (1.f / Dc);
        const float rstd0 = rsqrtf(sqred[r] * (1.f / Dc) - mean0 * mean0 + 1e-5f);
        const float mean1 = sred[r + 8] * (1.f / Dc);
        const float rstd1 = rsqrtf(sqred[r + 8] * (1.f / Dc) - mean1 * mean1 + 1e-5f);
#pragma unroll
        for (int nt = 0; nt < 8; ++nt) {
            const int col = wn + nt * 8 + 2 * (lane & 3);
            float gx = __ldg(gamma + col), gy = __ldg(gamma + col + 1);
            float bx = __ldg(beta + col), by = __ldg(beta + col + 1);
            float o0 = (acc[mt][nt][0] - mean0) * rstd0 * gx + bx;
            float o1 = (acc[mt][nt][1] - mean0) * rstd0 * gy + by;
            float o2 = (acc[mt][nt][2] - mean1) * rstd1 * gx + bx;
            float o3 = (acc[mt][nt][3] - mean1) * rstd1 * gy + by;
            *(float2*)(outf + (size_t)(m0 + r) * Dc + col) = make_float2(o0, o1);
            *(float2*)(outf + (size_t)(m0 + r + 8) * Dc + col) = make_float2(o2, o3);
            if (outh) {
                *(__half2*)(outh + (size_t)(m0 + r) * Dc + col) = __floats2half2_rn(o0, o1);
                *(__half2*)(outh + (size_t)(m0 + r + 8) * Dc + col) = __floats2half2_rn(o2, o3);
            }
        }
    }
}

// ---------------- V transpose ----------------
__global__ __launch_bounds__(256) void vt_pack(const __half* __restrict__ qkvh) {
    __shared__ __half tile[64][72];
    const int bh = blockIdx.y, b = bh >> 2, h = bh & 3;
    const int k0 = blockIdx.x * 64;
    const int t = threadIdx.x;
#pragma unroll
    for (int i = 0; i < 16; ++i) {
        int idx = t + i * 256, kk = idx >> 6, d = idx & 63;
        tile[kk][d] = qkvh[(size_t)(b * Tc + k0 + kk) * 768 + 512 + h * 64 + d];
    }
    __syncthreads();
#pragma unroll
    for (int i = 0; i < 16; ++i) {
        int idx = t + i * 256, d = idx >> 6, kk = idx & 63;
        g_vth[(size_t)bh * 64 * Tc + (size_t)d * Tc + k0 + kk] = tile[kk][d];
    }
}

// ---------------- small kernels ----------------
__global__ void f2h_k(const float* __restrict__ s, __half* __restrict__ d, int n2) {
    int i = blockIdx.x * 256 + threadIdx.x;
    if (i < n2) {
        float2 v = ((const float2*)s)[i];
        ((__half2*)d)[i] = __floats2half2_rn(v.x, v.y);
    }
}
__global__ void zero_k() {
    int i = blockIdx.x * 256 + threadIdx.x;
    if (i < Bc * Tc) g_hraw[i] = 0.f;
}

__global__ __launch_bounds__(256) void halting_k(const float* __restrict__ mask, float* __restrict__ out) {
    const int b = blockIdx.x;
    const int t = threadIdx.x;
    __shared__ float es[Tc];
    __shared__ float redm[8], reds[8];
    float lmax = -3.4e38f;
    for (int k = t; k < Tc; k += 256) {
        float v = g_hraw[b * Tc + k] + mask[b * Tc + k] * (-1e10f);
        es[k] = v;
        lmax = fmaxf(lmax, v);
    }
#pragma unroll
    for (int o = 16; o; o >>= 1) lmax = fmaxf(lmax, __shfl_xor_sync(~0u, lmax, o));
    if ((t & 31) == 0) redm[t >> 5] = lmax;
    __syncthreads();
    float bmax = redm[0];
#pragma unroll
    for (int j = 1; j < 8; ++j) bmax = fmaxf(bmax, redm[j]);
    float lsum = 0.f;
    for (int k = t; k < Tc; k += 256) {
        float e = __expf(es[k] - bmax);
        es[k] = e;
        lsum += e;
    }
#pragma unroll
    for (int o = 16; o; o >>= 1) lsum += __shfl_xor_sync(~0u, lsum, o);
    if ((t & 31) == 0) reds[t >> 5] = lsum;
    __syncthreads();
    float bsum = 0.f;
#pragma unroll
    for (int j = 0; j < 8; ++j) bsum += reds[j];
    const float inv = 1.f / bsum;
    for (int k = t; k < Tc; k += 256) out[b * Tc + k] = es[k] * inv;
}

// =====================================================================
extern "C" void kernel_launch(void* const* d_in, const int* in_sizes, int n_in,
                              void* d_out, int out_size) {
    (void)in_sizes; (void)n_in; (void)out_size;
    const float* x    = (const float*)d_in[0];
    const float* mask = (const float*)d_in[1];
    const float* Wqkv = (const float*)d_in[2];
    const float* bqkv = (const float*)d_in[3];
    const float* Wo   = (const float*)d_in[4];
    const float* bo   = (const float*)d_in[5];
    const float* W1   = (const float*)d_in[6];
    const float* b1   = (const float*)d_in[7];
    const float* W2   = (const float*)d_in[8];
    const float* b2   = (const float*)d_in[9];
    const float* g1   = (const float*)d_in[10];
    const float* be1  = (const float*)d_in[11];
    const float* g2   = (const float*)d_in[12];
    const float* be2  = (const float*)d_in[13];
    float* out  = (float*)d_out;
    float* halt = out + (size_t)Bc * Tc * Dc;

    __half *p_xh, *p_qkvh, *p_attnh, *p_hh, *p_fh, *p_wqkvh, *p_woh, *p_w1h, *p_w2h;
    float *p_h;
    cudaGetSymbolAddress((void**)&p_xh, g_xh);
    cudaGetSymbolAddress((void**)&p_qkvh, g_qkvh);
    cudaGetSymbolAddress((void**)&p_attnh, g_attnh);
    cudaGetSymbolAddress((void**)&p_hh, g_hh);
    cudaGetSymbolAddress((void**)&p_fh, g_fh);
    cudaGetSymbolAddress((void**)&p_wqkvh, g_wqkvh);
    cudaGetSymbolAddress((void**)&p_woh, g_woh);
    cudaGetSymbolAddress((void**)&p_w1h, g_w1h);
    cudaGetSymbolAddress((void**)&p_w2h, g_w2h);
    cudaGetSymbolAddress((void**)&p_h, g_h);

    const int SMEM_128 = 65536;
    const int SMEM_AT  = 74752;
    const int SMEM_LN  = 82432;
    cudaFuncSetAttribute(gemm_proj_k, cudaFuncAttributeMaxDynamicSharedMemorySize, SMEM_128);
    cudaFuncSetAttribute(attn2_k,     cudaFuncAttributeMaxDynamicSharedMemorySize, SMEM_AT);
    cudaFuncSetAttribute(gemm_ln_k,   cudaFuncAttributeMaxDynamicSharedMemorySize, SMEM_LN);

    const int MR = Bc * Tc;  // 16384

    zero_k<<<64, 256>>>();
    f2h_k<<<(MR * Dc / 2 + 255) / 256, 256>>>(x, p_xh, MR * Dc / 2);
    f2h_k<<<(3 * Dc * Dc / 2 + 255) / 256, 256>>>(Wqkv, p_wqkvh, 3 * Dc * Dc / 2);
    f2h_k<<<(Dc * Dc / 2 + 255) / 256, 256>>>(Wo, p_woh, Dc * Dc / 2);
    f2h_k<<<(FFNc * Dc / 2 + 255) / 256, 256>>>(W1, p_w1h, FFNc * Dc / 2);
    f2h_k<<<(Dc * FFNc / 2 + 255) / 256, 256>>>(W2, p_w2h, Dc * FFNc / 2);
    // QKV projection -> fp16
    gemm_proj_k<<<dim3(6, MR / 128), 256, SMEM_128>>>(p_xh, p_wqkvh, bqkv, p_qkvh,
                                                      Dc, Dc, 3 * Dc, Dc, 0);
    vt_pack<<<dim3(Tc / 64, Bc * Hc), 256>>>(p_qkvh);
    // merged attention: attn (normalized) + halting colsums
    attn2_k<<<dim3(Tc / 128, Bc * Hc), 256, SMEM_AT>>>(p_qkvh, mask);
    halting_k<<<Bc, 256>>>(mask, halt);
    // Wo + residual(x) + LN1 -> h (fp32 + fp16)
    gemm_ln_k<<<MR / 64, 256, SMEM_LN>>>(p_attnh, p_woh, bo, x, g1, be1, p_h, p_hh, Dc, Dc);
    // FFN up + ReLU
    gemm_proj_k<<<dim3(8, MR / 128), 256, SMEM_128>>>(p_hh, p_w1h, b1, p_fh,
                                                      Dc, Dc, FFNc, Dc, 1);
    // W2 + residual(h) + LN2 -> out
    gemm_ln_k<<<MR / 64, 256, SMEM_LN>>>(p_fh, p_w2h, b2, p_h, g2, be2, out, nullptr, FFNc, FFNc);
}

// round 6
// speedup vs baseline: 6.3395x; 1.1111x over previous
#include <cuda_runtime.h>
#include <cuda_fp16.h>
#include <cstdint>
#include <cstddef>

#define Bc 8
#define Tc 2048
#define Dc 256
#define Hc 4
#define FFNc 1024

// ---------------- scratch (static device arrays) ----------------
__device__ __half g_xh[(size_t)Bc * Tc * Dc];
__device__ __half g_qkvh[(size_t)Bc * Tc * 3 * Dc];
__device__ __half g_vth[(size_t)Bc * Hc * 64 * Tc];     // V^T fp16 [bh][d][k]
__device__ __half g_attnh[(size_t)Bc * Tc * Dc];
__device__ __half g_hh[(size_t)Bc * Tc * Dc];
__device__ __half g_fh[(size_t)Bc * Tc * FFNc];
__device__ __half g_wqkvh[3 * Dc * Dc];
__device__ __half g_woh[Dc * Dc];
__device__ __half g_w1h[FFNc * Dc];
__device__ __half g_w2h[Dc * FFNc];
__device__ float g_h[(size_t)Bc * Tc * Dc];
__device__ float g_hraw[Bc * Tc];

// ---------------- helpers ----------------
__device__ __forceinline__ uint32_t s2u(const void* p) {
    uint32_t a;
    asm("{ .reg .u64 t; cvta.to.shared.u64 t, %1; cvt.u32.u64 %0, t; }" : "=r"(a) : "l"(p));
    return a;
}
__device__ __forceinline__ float ex2(float x) {
    float r;
    asm("ex2.approx.ftz.f32 %0, %1;" : "=f"(r) : "f"(x));
    return r;
}
#define EXPC 0.18033688011112042f   // 0.125 * log2(e)
#define CP_ASYNC16(dst, src) \
    asm volatile("cp.async.cg.shared.global [%0], [%1], 16;" :: "r"(dst), "l"(src))

__device__ __forceinline__ void ldm_x4(uint32_t* r, uint32_t addr) {
    asm volatile("ldmatrix.sync.aligned.m8n8.x4.shared.b16 {%0,%1,%2,%3}, [%4];"
                 : "=r"(r[0]), "=r"(r[1]), "=r"(r[2]), "=r"(r[3]) : "r"(addr));
}
__device__ __forceinline__ void mma16816(float* c, const uint32_t* a, const uint32_t* b) {
    asm volatile("mma.sync.aligned.m16n8k16.row.col.f32.f16.f16.f32 "
                 "{%0,%1,%2,%3}, {%4,%5,%6,%7}, {%8,%9}, {%0,%1,%2,%3};"
                 : "+f"(c[0]), "+f"(c[1]), "+f"(c[2]), "+f"(c[3])
                 : "r"(a[0]), "r"(a[1]), "r"(a[2]), "r"(a[3]), "r"(b[0]), "r"(b[1]));
}

// S-tile: acc[4][2][4] += A(128x64 smem, swz rows of 128B) @ B(64x64 smem)^T
__device__ __forceinline__ void stile64(uint32_t As, uint32_t Bs, float (&acc)[4][2][4],
                                        int lane, int wm, int wn) {
#pragma unroll
    for (int ks = 0; ks < 4; ++ks) {
        const int ck = ks * 2 + (lane >> 4);
        uint32_t af[4][4];
#pragma unroll
        for (int mt = 0; mt < 4; ++mt) {
            int m = wm + mt * 16 + (lane & 15);
            ldm_x4(af[mt], As + m * 128 + ((ck ^ (m & 7)) << 4));
        }
        uint32_t bf[2][2];
        {
            uint32_t r4[4];
            int n = wn + (lane & 15);
            ldm_x4(r4, Bs + n * 128 + ((ck ^ (n & 7)) << 4));
            bf[0][0] = r4[0]; bf[0][1] = r4[2];
            bf[1][0] = r4[1]; bf[1][1] = r4[3];
        }
#pragma unroll
        for (int mt = 0; mt < 4; ++mt)
#pragma unroll
            for (int nt = 0; nt < 2; ++nt) mma16816(acc[mt][nt], af[mt], bf[nt]);
    }
}

// ---------------- merged attention: denominators, then normalized PV + colsum ----------------
// grid (16 q-tiles, 32 bh), 256 threads, target 2 CTAs/SM.
__global__ __launch_bounds__(256, 2) void attn2_k(const __half* __restrict__ qkvh,
                                                  const float* __restrict__ mask) {
    extern __shared__ char sm[];
    const uint32_t S0 = s2u(sm);
    const uint32_t Qs = S0, Ks = S0 + 16384, Vs = S0 + 32768, Es = S0 + 49152;
    float* msk = (float*)(sm + 65536);       // 2048 floats: additive offsets 0 / -1000
    float* dsum = (float*)(sm + 73728);      // 128
    float* l2d_sm = (float*)(sm + 74240);    // 128: -log2(denominator)
    const int tid = threadIdx.x, lane = tid & 31, wid = tid >> 5;
    const int bh = blockIdx.y, b = bh >> 2, h = bh & 3;
    const int m0 = blockIdx.x * 128;
    const int wm = (wid >> 2) * 64, wn = (wid & 3) * 16;

    for (int i = tid; i < Tc; i += 256) msk[i] = (mask[b * Tc + i] > 0.5f) ? -1000.f : 0.f;
    if (tid < 128) dsum[tid] = 0.f;

    {   // Q tile (persistent)
        const __half* q0 = qkvh + ((size_t)(b * Tc + m0)) * 768 + h * 64;
#pragma unroll
        for (int i = 0; i < 4; ++i) {
            int ch = i * 256 + tid, r = ch >> 3, c = ch & 7;
            CP_ASYNC16(Qs + r * 128 + ((c ^ (r & 7)) << 4), q0 + (size_t)r * 768 + c * 8);
        }
    }
    auto loadK = [&](int kt, int buf) {
        const __half* kg = qkvh + ((size_t)(b * Tc + kt * 64)) * 768 + 256 + h * 64;
#pragma unroll
        for (int i = 0; i < 2; ++i) {
            int ch = i * 256 + tid, r = ch >> 3, c = ch & 7;
            CP_ASYNC16(Ks + buf * 8192 + r * 128 + ((c ^ (r & 7)) << 4), kg + (size_t)r * 768 + c * 8);
        }
    };
    auto loadKV = [&](int kt, int buf) {
        const int k0 = kt * 64;
        const __half* kg = qkvh + ((size_t)(b * Tc + k0)) * 768 + 256 + h * 64;
        const __half* vg = g_vth + (size_t)bh * 64 * Tc + k0;
#pragma unroll
        for (int i = 0; i < 2; ++i) {
            int ch = i * 256 + tid, r = ch >> 3, c = ch & 7;
            uint32_t off = r * 128 + ((c ^ (r & 7)) << 4);
            CP_ASYNC16(Ks + buf * 8192 + off, kg + (size_t)r * 768 + c * 8);
            CP_ASYNC16(Vs + buf * 8192 + off, vg + (size_t)r * Tc + c * 8);
        }
    };

    // ---- loop A: denominators only ----
    loadK(0, 0);
    asm volatile("cp.async.commit_group;");
    float dacc[4][2];
#pragma unroll
    for (int mt = 0; mt < 4; ++mt) dacc[mt][0] = dacc[mt][1] = 0.f;

    const int cbase = wn + 2 * (lane & 3);
    for (int kt = 0; kt < 32; ++kt) {
        const int buf = kt & 1;
        asm volatile("cp.async.wait_group 0;");
        __syncthreads();
        float sacc[4][2][4];
#pragma unroll
        for (int mt = 0; mt < 4; ++mt)
#pragma unroll
            for (int nt = 0; nt < 2; ++nt)
#pragma unroll
                for (int i = 0; i < 4; ++i) sacc[mt][nt][i] = 0.f;
        stile64(Qs, Ks + buf * 8192, sacc, lane, wm, wn);
        if (kt + 1 < 32) {
            loadK(kt + 1, buf ^ 1);
            asm volatile("cp.async.commit_group;");
        }
        const int k0 = kt * 64;
        float mo[4] = {msk[k0 + cbase], msk[k0 + cbase + 1],
                       msk[k0 + cbase + 8], msk[k0 + cbase + 9]};
#pragma unroll
        for (int mt = 0; mt < 4; ++mt)
#pragma unroll
            for (int nt = 0; nt < 2; ++nt) {
                dacc[mt][0] += ex2(fmaf(sacc[mt][nt][0], EXPC, mo[2 * nt]))
                             + ex2(fmaf(sacc[mt][nt][1], EXPC, mo[2 * nt + 1]));
                dacc[mt][1] += ex2(fmaf(sacc[mt][nt][2], EXPC, mo[2 * nt]))
                             + ex2(fmaf(sacc[mt][nt][3], EXPC, mo[2 * nt + 1]));
            }
    }
#pragma unroll
    for (int mt = 0; mt < 4; ++mt) {
        float d0 = dacc[mt][0], d1 = dacc[mt][1];
        d0 += __shfl_xor_sync(~0u, d0, 1); d0 += __shfl_xor_sync(~0u, d0, 2);
        d1 += __shfl_xor_sync(~0u, d1, 1); d1 += __shfl_xor_sync(~0u, d1, 2);
        if ((lane & 3) == 0) {
            atomicAdd(&dsum[wm + mt * 16 + (lane >> 2)], d0);
            atomicAdd(&dsum[wm + mt * 16 + (lane >> 2) + 8], d1);
        }
    }
    __syncthreads();
    if (tid < 128) l2d_sm[tid] = -__log2f(dsum[tid]);
    __syncthreads();

    float l2r0[4], l2r1[4];
#pragma unroll
    for (int mt = 0; mt < 4; ++mt) {
        const int r = wm + mt * 16 + (lane >> 2);
        l2r0[mt] = l2d_sm[r];
        l2r1[mt] = l2d_sm[r + 8];
    }

    // ---- loop B: normalized weights -> PV + halting colsum ----
    loadKV(0, 0);
    asm volatile("cp.async.commit_group;");
    float pacc[4][2][4];
#pragma unroll
    for (int mt = 0; mt < 4; ++mt)
#pragma unroll
        for (int nt = 0; nt < 2; ++nt)
#pragma unroll
            for (int i = 0; i < 4; ++i) pacc[mt][nt][i] = 0.f;

    for (int kt = 0; kt < 32; ++kt) {
        const int buf = kt & 1;
        asm volatile("cp.async.wait_group 0;");
        __syncthreads();
        float sacc[4][2][4];
#pragma unroll
        for (int mt = 0; mt < 4; ++mt)
#pragma unroll
            for (int nt = 0; nt < 2; ++nt)
#pragma unroll
                for (int i = 0; i < 4; ++i) sacc[mt][nt][i] = 0.f;
        stile64(Qs, Ks + buf * 8192, sacc, lane, wm, wn);
        if (kt + 1 < 32) {
            loadKV(kt + 1, buf ^ 1);
            asm volatile("cp.async.commit_group;");
        }
        const int k0 = kt * 64;
        float mo[4] = {msk[k0 + cbase], msk[k0 + cbase + 1],
                       msk[k0 + cbase + 8], msk[k0 + cbase + 9]};
        float cp[2][2] = {{0.f, 0.f}, {0.f, 0.f}};
#pragma unroll
        for (int mt = 0; mt < 4; ++mt) {
            const int r = wm + mt * 16 + (lane >> 2);
#pragma unroll
            for (int nt = 0; nt < 2; ++nt) {
                const int c = wn + nt * 8 + 2 * (lane & 3);
                float w0 = ex2(fmaf(sacc[mt][nt][0], EXPC, mo[2 * nt] + l2r0[mt]));
                float w1 = ex2(fmaf(sacc[mt][nt][1], EXPC, mo[2 * nt + 1] + l2r0[mt]));
                float w2 = ex2(fmaf(sacc[mt][nt][2], EXPC, mo[2 * nt] + l2r1[mt]));
                float w3 = ex2(fmaf(sacc[mt][nt][3], EXPC, mo[2 * nt + 1] + l2r1[mt]));
                cp[nt][0] += w0 + w2;
                cp[nt][1] += w1 + w3;
                const uint32_t chunk = (uint32_t)(c >> 3);
                const uint32_t rem = (uint32_t)((c * 2) & 15);
                uint32_t a0 = Es + r * 128 + ((chunk ^ (r & 7)) << 4) + rem;
                uint32_t a1 = Es + (r + 8) * 128 + ((chunk ^ ((r + 8) & 7)) << 4) + rem;
                __half2 h0 = __floats2half2_rn(w0, w1);
                __half2 h1 = __floats2half2_rn(w2, w3);
                asm volatile("st.shared.b32 [%0], %1;" :: "r"(a0), "r"(*(uint32_t*)&h0));
                asm volatile("st.shared.b32 [%0], %1;" :: "r"(a1), "r"(*(uint32_t*)&h1));
            }
        }
#pragma unroll
        for (int nt = 0; nt < 2; ++nt)
#pragma unroll
            for (int j = 0; j < 2; ++j) {
                float v = cp[nt][j];
                v += __shfl_xor_sync(~0u, v, 4);
                v += __shfl_xor_sync(~0u, v, 8);
                v += __shfl_xor_sync(~0u, v, 16);
                if (lane < 4) {
                    const int c = wn + nt * 8 + 2 * lane + j;
                    atomicAdd(&g_hraw[b * Tc + k0 + c], 0.25f * v);
                }
            }
        __syncthreads();
        stile64(Es, Vs + buf * 8192, pacc, lane, wm, wn);
    }

    // pacc is already normalized
#pragma unroll
    for (int mt = 0; mt < 4; ++mt) {
        const int r = wm + mt * 16 + (lane >> 2);
#pragma unroll
        for (int nt = 0; nt < 2; ++nt) {
            const int c = wn + nt * 8 + 2 * (lane & 3);
            *(__half2*)(g_attnh + (size_t)(b * Tc + m0 + r) * Dc + h * 64 + c) =
                __floats2half2_rn(pacc[mt][nt][0], pacc[mt][nt][1]);
            *(__half2*)(g_attnh + (size_t)(b * Tc + m0 + r + 8) * Dc + h * 64 + c) =
                __floats2half2_rn(pacc[mt][nt][2], pacc[mt][nt][3]);
        }
    }
}

// ---------------- fp16 mma.sync GEMM core (BM=128, BN=128) ----------------
__device__ __forceinline__ void gemm_core128(const __half* __restrict__ Ag, int lda,
                                             const __half* __restrict__ Bg, int ldb,
                                             int K, int m0, int n0,
                                             float (&acc)[4][4][4]) {
    extern __shared__ char smem_raw[];
    const int tid = threadIdx.x, lane = tid & 31, wid = tid >> 5;
    const int wm = (wid >> 2) * 64;
    const int wn = (wid & 3) * 32;
    const uint32_t sA = s2u(smem_raw);
    const uint32_t sB = sA + 2 * 128 * 128;
    const int NKT = K >> 6;

#pragma unroll
    for (int mt = 0; mt < 4; ++mt)
#pragma unroll
        for (int nt = 0; nt < 4; ++nt)
#pragma unroll
            for (int i = 0; i < 4; ++i) acc[mt][nt][i] = 0.f;

    auto loadA = [&](int kt, int buf) {
        const __half* s0 = Ag + (size_t)m0 * lda + kt * 64;
        uint32_t d0 = sA + buf * (128 * 128);
#pragma unroll
        for (int i = 0; i < 4; ++i) {
            int ch = i * 256 + tid, r = ch >> 3, c = ch & 7;
            CP_ASYNC16(d0 + r * 128 + ((c ^ (r & 7)) << 4), s0 + (size_t)r * lda + c * 8);
        }
    };
    auto loadB = [&](int kt, int buf) {
        const __half* s0 = Bg + (size_t)n0 * ldb + kt * 64;
        uint32_t d0 = sB + buf * (128 * 128);
#pragma unroll
        for (int i = 0; i < 4; ++i) {
            int ch = i * 256 + tid, r = ch >> 3, c = ch & 7;
            CP_ASYNC16(d0 + r * 128 + ((c ^ (r & 7)) << 4), s0 + (size_t)r * ldb + c * 8);
        }
    };

    loadA(0, 0); loadB(0, 0);
    asm volatile("cp.async.commit_group;");

    for (int t = 0; t < NKT; ++t) {
        const int buf = t & 1;
        if (t + 1 < NKT) {
            loadA(t + 1, buf ^ 1); loadB(t + 1, buf ^ 1);
            asm volatile("cp.async.commit_group;");
            asm volatile("cp.async.wait_group 1;");
        } else {
            asm volatile("cp.async.wait_group 0;");
        }
        __syncthreads();
        const uint32_t cA = sA + buf * (128 * 128);
        const uint32_t cB = sB + buf * (128 * 128);
#pragma unroll
        for (int ks = 0; ks < 4; ++ks) {
            uint32_t af[4][4];
#pragma unroll
            for (int mt = 0; mt < 4; ++mt) {
                int m = wm + mt * 16 + (lane & 15);
                int ck = ks * 2 + (lane >> 4);
                ldm_x4(af[mt], cA + m * 128 + ((ck ^ (m & 7)) << 4));
            }
            uint32_t bf[4][2];
#pragma unroll
            for (int g = 0; g < 2; ++g) {
                uint32_t r4[4];
                int n = wn + g * 16 + (lane & 15);
                int ck = ks * 2 + (lane >> 4);
                ldm_x4(r4, cB + n * 128 + ((ck ^ (n & 7)) << 4));
                bf[2 * g][0] = r4[0]; bf[2 * g][1] = r4[2];
                bf[2 * g + 1][0] = r4[1]; bf[2 * g + 1][1] = r4[3];
            }
#pragma unroll
            for (int mt = 0; mt < 4; ++mt)
#pragma unroll
                for (int nt = 0; nt < 4; ++nt) mma16816(acc[mt][nt], af[mt], bf[nt]);
        }
        __syncthreads();
    }
}

__global__ __launch_bounds__(256) void gemm_proj_k(const __half* __restrict__ A,
                                                   const __half* __restrict__ Bw,
                                                   const float* __restrict__ bias,
                                                   __half* __restrict__ Ch,
                                                   int lda, int ldb, int ldc, int K, int relu) {
    float acc[4][4][4];
    const int m0 = blockIdx.y * 128, n0 = blockIdx.x * 128;
    gemm_core128(A, lda, Bw, ldb, K, m0, n0, acc);
    const int lane = threadIdx.x & 31, wid = threadIdx.x >> 5;
    const int wm = (wid >> 2) * 64, wn = (wid & 3) * 32;
#pragma unroll
    for (int mt = 0; mt < 4; ++mt) {
        int r = m0 + wm + mt * 16 + (lane >> 2);
#pragma unroll
        for (int nt = 0; nt < 4; ++nt) {
            int col = n0 + wn + nt * 8 + 2 * (lane & 3);
            float bx = __ldg(bias + col), by = __ldg(bias + col + 1);
            float v0 = acc[mt][nt][0] + bx, v1 = acc[mt][nt][1] + by;
            float v2 = acc[mt][nt][2] + bx, v3 = acc[mt][nt][3] + by;
            if (relu) {
                v0 = fmaxf(v0, 0.f); v1 = fmaxf(v1, 0.f);
                v2 = fmaxf(v2, 0.f); v3 = fmaxf(v3, 0.f);
            }
            *(__half2*)(Ch + (size_t)r * ldc + col) = __floats2half2_rn(v0, v1);
            *(__half2*)(Ch + (size_t)(r + 8) * ldc + col) = __floats2half2_rn(v2, v3);
        }
    }
}

// ---------------- GEMM (BM=64, BN=256=N) + bias + residual + LayerNorm ----------------
__global__ __launch_bounds__(256) void gemm_ln_k(const __half* __restrict__ A,
                                                 const __half* __restrict__ Bw,
                                                 const float* __restrict__ bias,
                                                 const float* __restrict__ res,
                                                 const float* __restrict__ gamma,
                                                 const float* __restrict__ beta,
                                                 float* __restrict__ outf,
                                                 __half* __restrict__ outh,
                                                 int lda, int K) {
    extern __shared__ char sm[];
    const uint32_t sA = s2u(sm);               // 2 x 8192
    const uint32_t sB = sA + 16384;            // 2 x 32768
    float* sred = (float*)(sm + 16384 + 65536);
    float* sqred = sred + 64;
    const int tid = threadIdx.x, lane = tid & 31, wid = tid >> 5;
    const int m0 = blockIdx.x * 64;
    const int wm = (wid >> 2) * 32, wn = (wid & 3) * 64;
    const int NKT = K >> 6;

    float acc[2][8][4];
#pragma unroll
    for (int mt = 0; mt < 2; ++mt)
#pragma unroll
        for (int nt = 0; nt < 8; ++nt)
#pragma unroll
            for (int i = 0; i < 4; ++i) acc[mt][nt][i] = 0.f;

    auto loadA = [&](int kt, int buf) {
        const __half* s0 = A + (size_t)m0 * lda + kt * 64;
        uint32_t d0 = sA + buf * 8192;
#pragma unroll
        for (int i = 0; i < 2; ++i) {
            int ch = i * 256 + tid, r = ch >> 3, c = ch & 7;
            CP_ASYNC16(d0 + r * 128 + ((c ^ (r & 7)) << 4), s0 + (size_t)r * lda + c * 8);
        }
    };
    auto loadB = [&](int kt, int buf) {
        const __half* s0 = Bw + kt * 64;
        uint32_t d0 = sB + buf * 32768;
#pragma unroll
        for (int i = 0; i < 8; ++i) {
            int ch = i * 256 + tid, r = ch >> 3, c = ch & 7;
            CP_ASYNC16(d0 + r * 128 + ((c ^ (r & 7)) << 4), s0 + (size_t)r * K + c * 8);
        }
    };

    loadA(0, 0); loadB(0, 0);
    asm volatile("cp.async.commit_group;");

    for (int t = 0; t < NKT; ++t) {
        const int buf = t & 1;
        if (t + 1 < NKT) {
            loadA(t + 1, buf ^ 1); loadB(t + 1, buf ^ 1);
            asm volatile("cp.async.commit_group;");
            asm volatile("cp.async.wait_group 1;");
        } else {
            asm volatile("cp.async.wait_group 0;");
        }
        __syncthreads();
        const uint32_t cA = sA + buf * 8192;
        const uint32_t cB = sB + buf * 32768;
#pragma unroll
        for (int ks = 0; ks < 4; ++ks) {
            const int ck = ks * 2 + (lane >> 4);
            uint32_t af[2][4];
#pragma unroll
            for (int mt = 0; mt < 2; ++mt) {
                int m = wm + mt * 16 + (lane & 15);
                ldm_x4(af[mt], cA + m * 128 + ((ck ^ (m & 7)) << 4));
            }
            uint32_t bf[8][2];
#pragma unroll
            for (int g = 0; g < 4; ++g) {
                uint32_t r4[4];
                int n = wn + g * 16 + (lane & 15);
                ldm_x4(r4, cB + n * 128 + ((ck ^ (n & 7)) << 4));
                bf[2 * g][0] = r4[0]; bf[2 * g][1] = r4[2];
                bf[2 * g + 1][0] = r4[1]; bf[2 * g + 1][1] = r4[3];
            }
#pragma unroll
            for (int mt = 0; mt < 2; ++mt)
#pragma unroll
                for (int nt = 0; nt < 8; ++nt) mma16816(acc[mt][nt], af[mt], bf[nt]);
        }
        __syncthreads();
    }

    // ---- epilogue: bias + residual, LN stats, normalize ----
    if (tid < 64) { sred[tid] = 0.f; sqred[tid] = 0.f; }
    __syncthreads();
#pragma unroll
    for (int mt = 0; mt < 2; ++mt) {
        const int r = wm + mt * 16 + (lane >> 2);
        float s0 = 0.f, sq0 = 0.f, s1 = 0.f, sq1 = 0.f;
#pragma unroll
        for (int nt = 0; nt < 8; ++nt) {
            const int col = wn + nt * 8 + 2 * (lane & 3);
            float bx = __ldg(bias + col), by = __ldg(bias + col + 1);
            float2 r0 = *(const float2*)(res + (size_t)(m0 + r) * Dc + col);
            float2 r1 = *(const float2*)(res + (size_t)(m0 + r + 8) * Dc + col);
            float v0 = acc[mt][nt][0] + bx + r0.x;
            float v1 = acc[mt][nt][1] + by + r0.y;
            float v2 = acc[mt][nt][2] + bx + r1.x;
            float v3 = acc[mt][nt][3] + by + r1.y;
            acc[mt][nt][0] = v0; acc[mt][nt][1] = v1;
            acc[mt][nt][2] = v2; acc[mt][nt][3] = v3;
            s0 += v0 + v1; sq0 += v0 * v0 + v1 * v1;
            s1 += v2 + v3; sq1 += v2 * v2 + v3 * v3;
        }
        s0 += __shfl_xor_sync(~0u, s0, 1); s0 += __shfl_xor_sync(~0u, s0, 2);
        sq0 += __shfl_xor_sync(~0u, sq0, 1); sq0 += __shfl_xor_sync(~0u, sq0, 2);
        s1 += __shfl_xor_sync(~0u, s1, 1); s1 += __shfl_xor_sync(~0u, s1, 2);
        sq1 += __shfl_xor_sync(~0u, sq1, 1); sq1 += __shfl_xor_sync(~0u, sq1, 2);
        if ((lane & 3) == 0) {
            atomicAdd(&sred[r], s0); atomicAdd(&sqred[r], sq0);
            atomicAdd(&sred[r + 8], s1); atomicAdd(&sqred[r + 8], sq1);
        }
    }
    __syncthreads();
#pragma unroll
    for (int mt = 0; mt < 2; ++mt) {
        const int r = wm + mt * 16 + (lane >> 2);
        const float mean0 = sred[r] * (1.f / Dc);
        const float rstd0 = rsqrtf(sqred[r] * (1.f / Dc) - mean0 * mean0 + 1e-5f);
        const float mean1 = sred[r + 8] * (1.f / Dc);
        const float rstd1 = rsqrtf(sqred[r + 8] * (1.f / Dc) - mean1 * mean1 + 1e-5f);
#pragma unroll
        for (int nt = 0; nt < 8; ++nt) {
            const int col = wn + nt * 8 + 2 * (lane & 3);
            float gx = __ldg(gamma + col), gy = __ldg(gamma + col + 1);
            float bx = __ldg(beta + col), by = __ldg(beta + col + 1);
            float o0 = (acc[mt][nt][0] - mean0) * rstd0 * gx + bx;
            float o1 = (acc[mt][nt][1] - mean0) * rstd0 * gy + by;
            float o2 = (acc[mt][nt][2] - mean1) * rstd1 * gx + bx;
            float o3 = (acc[mt][nt][3] - mean1) * rstd1 * gy + by;
            *(float2*)(outf + (size_t)(m0 + r) * Dc + col) = make_float2(o0, o1);
            *(float2*)(outf + (size_t)(m0 + r + 8) * Dc + col) = make_float2(o2, o3);
            if (outh) {
                *(__half2*)(outh + (size_t)(m0 + r) * Dc + col) = __floats2half2_rn(o0, o1);
                *(__half2*)(outh + (size_t)(m0 + r + 8) * Dc + col) = __floats2half2_rn(o2, o3);
            }
        }
    }
}

// ---------------- V transpose ----------------
__global__ __launch_bounds__(256) void vt_pack(const __half* __restrict__ qkvh) {
    __shared__ __half tile[64][72];
    const int bh = blockIdx.y, b = bh >> 2, h = bh & 3;
    const int k0 = blockIdx.x * 64;
    const int t = threadIdx.x;
#pragma unroll
    for (int i = 0; i < 16; ++i) {
        int idx = t + i * 256, kk = idx >> 6, d = idx & 63;
        tile[kk][d] = qkvh[(size_t)(b * Tc + k0 + kk) * 768 + 512 + h * 64 + d];
    }
    __syncthreads();
#pragma unroll
    for (int i = 0; i < 16; ++i) {
        int idx = t + i * 256, d = idx >> 6, kk = idx & 63;
        g_vth[(size_t)bh * 64 * Tc + (size_t)d * Tc + k0 + kk] = tile[kk][d];
    }
}

// ---------------- one merged pack kernel: all f2h conversions + hraw zero ----------------
// segment boundaries in float2 units
#define SEG0 2097152u   // x           (4,194,304 floats)
#define SEG1 2195456u   // + Wqkv      (196,608)
#define SEG2 2228224u   // + Wo        (65,536)
#define SEG3 2359296u   // + W1        (262,144)
#define SEG4 2490368u   // + W2        (262,144)
__global__ __launch_bounds__(256) void pack_all(const float* __restrict__ x,
                                                const float* __restrict__ Wqkv,
                                                const float* __restrict__ Wo,
                                                const float* __restrict__ W1,
                                                const float* __restrict__ W2) {
    uint32_t i = blockIdx.x * 256 + threadIdx.x;
    if (i < Bc * Tc / 2) ((float2*)g_hraw)[i] = make_float2(0.f, 0.f);
    const float2* s;
    __half2* d;
    uint32_t off;
    if (i < SEG0)      { s = (const float2*)x;    d = (__half2*)g_xh;    off = i; }
    else if (i < SEG1) { s = (const float2*)Wqkv; d = (__half2*)g_wqkvh; off = i - SEG0; }
    else if (i < SEG2) { s = (const float2*)Wo;   d = (__half2*)g_woh;   off = i - SEG1; }
    else if (i < SEG3) { s = (const float2*)W1;   d = (__half2*)g_w1h;   off = i - SEG2; }
    else if (i < SEG4) { s = (const float2*)W2;   d = (__half2*)g_w2h;   off = i - SEG3; }
    else return;
    float2 v = s[off];
    d[off] = __floats2half2_rn(v.x, v.y);
}

__global__ __launch_bounds__(256) void halting_k(const float* __restrict__ mask, float* __restrict__ out) {
    const int b = blockIdx.x;
    const int t = threadIdx.x;
    __shared__ float es[Tc];
    __shared__ float redm[8], reds[8];
    float lmax = -3.4e38f;
    for (int k = t; k < Tc; k += 256) {
        float v = g_hraw[b * Tc + k] + mask[b * Tc + k] * (-1e10f);
        es[k] = v;
        lmax = fmaxf(lmax, v);
    }
#pragma unroll
    for (int o = 16; o; o >>= 1) lmax = fmaxf(lmax, __shfl_xor_sync(~0u, lmax, o));
    if ((t & 31) == 0) redm[t >> 5] = lmax;
    __syncthreads();
    float bmax = redm[0];
#pragma unroll
    for (int j = 1; j < 8; ++j) bmax = fmaxf(bmax, redm[j]);
    float lsum = 0.f;
    for (int k = t; k < Tc; k += 256) {
        float e = __expf(es[k] - bmax);
        es[k] = e;
        lsum += e;
    }
#pragma unroll
    for (int o = 16; o; o >>= 1) lsum += __shfl_xor_sync(~0u, lsum, o);
    if ((t & 31) == 0) reds[t >> 5] = lsum;
    __syncthreads();
    float bsum = 0.f;
#pragma unroll
    for (int j = 0; j < 8; ++j) bsum += reds[j];
    const float inv = 1.f / bsum;
    for (int k = t; k < Tc; k += 256) out[b * Tc + k] = es[k] * inv;
}

// =====================================================================
extern "C" void kernel_launch(void* const* d_in, const int* in_sizes, int n_in,
                              void* d_out, int out_size) {
    (void)in_sizes; (void)n_in; (void)out_size;
    const float* x    = (const float*)d_in[0];
    const float* mask = (const float*)d_in[1];
    const float* Wqkv = (const float*)d_in[2];
    const float* bqkv = (const float*)d_in[3];
    const float* Wo   = (const float*)d_in[4];
    const float* bo   = (const float*)d_in[5];
    const float* W1   = (const float*)d_in[6];
    const float* b1   = (const float*)d_in[7];
    const float* W2   = (const float*)d_in[8];
    const float* b2   = (const float*)d_in[9];
    const float* g1   = (const float*)d_in[10];
    const float* be1  = (const float*)d_in[11];
    const float* g2   = (const float*)d_in[12];
    const float* be2  = (const float*)d_in[13];
    float* out  = (float*)d_out;
    float* halt = out + (size_t)Bc * Tc * Dc;

    __half *p_xh, *p_qkvh, *p_attnh, *p_hh, *p_fh, *p_wqkvh, *p_woh, *p_w1h, *p_w2h;
    float *p_h;
    cudaGetSymbolAddress((void**)&p_xh, g_xh);
    cudaGetSymbolAddress((void**)&p_qkvh, g_qkvh);
    cudaGetSymbolAddress((void**)&p_attnh, g_attnh);
    cudaGetSymbolAddress((void**)&p_hh, g_hh);
    cudaGetSymbolAddress((void**)&p_fh, g_fh);
    cudaGetSymbolAddress((void**)&p_wqkvh, g_wqkvh);
    cudaGetSymbolAddress((void**)&p_woh, g_woh);
    cudaGetSymbolAddress((void**)&p_w1h, g_w1h);
    cudaGetSymbolAddress((void**)&p_w2h, g_w2h);
    cudaGetSymbolAddress((void**)&p_h, g_h);

    const int SMEM_128 = 65536;
    const int SMEM_AT  = 74752;
    const int SMEM_LN  = 82432;
    cudaFuncSetAttribute(gemm_proj_k, cudaFuncAttributeMaxDynamicSharedMemorySize, SMEM_128);
    cudaFuncSetAttribute(attn2_k,     cudaFuncAttributeMaxDynamicSharedMemorySize, SMEM_AT);
    cudaFuncSetAttribute(gemm_ln_k,   cudaFuncAttributeMaxDynamicSharedMemorySize, SMEM_LN);

    const int MR = Bc * Tc;  // 16384

    // all fp32->fp16 packing + hraw zero in one kernel
    pack_all<<<(SEG4 + 255) / 256, 256>>>(x, Wqkv, Wo, W1, W2);
    // QKV projection -> fp16
    gemm_proj_k<<<dim3(6, MR / 128), 256, SMEM_128>>>(p_xh, p_wqkvh, bqkv, p_qkvh,
                                                      Dc, Dc, 3 * Dc, Dc, 0);
    vt_pack<<<dim3(Tc / 64, Bc * Hc), 256>>>(p_qkvh);
    // merged attention: attn (normalized) + halting colsums
    attn2_k<<<dim3(Tc / 128, Bc * Hc), 256, SMEM_AT>>>(p_qkvh, mask);
    halting_k<<<Bc, 256>>>(mask, halt);
    // Wo + residual(x) + LN1 -> h (fp32 + fp16)
    gemm_ln_k<<<MR / 64, 256, SMEM_LN>>>(p_attnh, p_woh, bo, x, g1, be1, p_h, p_hh, Dc, Dc);
    // FFN up + ReLU
    gemm_proj_k<<<dim3(8, MR / 128), 256, SMEM_128>>>(p_hh, p_w1h, b1, p_fh,
                                                      Dc, Dc, FFNc, Dc, 1);
    // W2 + residual(h) + LN2 -> out
    gemm_ln_k<<<MR / 64, 256, SMEM_LN>>>(p_fh, p_w2h, b2, p_h, g2, be2, out, nullptr, FFNc, FFNc);
}